// round 10
// baseline (speedup 1.0000x reference)
#include <cuda_runtime.h>
#include <math.h>

// ---------------- problem constants ----------------
#define TT 128
#define BB 256
#define HH 512
#define GG 2048
#define VV 128
#define LL 128
#define LDH (TT*BB)

typedef unsigned long long u64t;

__device__ __forceinline__ u64t pack2(float x, float y) {
    u64t r; asm("mov.b64 %0, {%1, %2};" : "=l"(r) : "f"(x), "f"(y)); return r;
}
__device__ __forceinline__ void fma2(u64t& d, u64t a, u64t b) {
    asm("fma.rn.f32x2 %0, %1, %2, %0;" : "+l"(d) : "l"(a), "l"(b));
}
__device__ __forceinline__ void add2(u64t& d, u64t a) {
    asm("add.rn.f32x2 %0, %0, %1;" : "+l"(d) : "l"(a));
}
__device__ __forceinline__ float2 unpack2(u64t v) {
    float2 r; asm("mov.b64 {%0, %1}, %2;" : "=f"(r.x), "=f"(r.y) : "l"(v)); return r;
}
__device__ __forceinline__ unsigned smem_u32(const void* p) {
    return (unsigned)__cvta_generic_to_shared(p);
}
#define CP16(dst, src) asm volatile("cp.async.ca.shared.global [%0], [%1], 16;" :: "r"(dst), "l"((const void*)(src)) : "memory")
#define CP_COMMIT      asm volatile("cp.async.commit_group;" ::: "memory")
#define CP_WAIT1       asm volatile("cp.async.wait_group 1;" ::: "memory")
#define CP_WAIT0       asm volatile("cp.async.wait_group 0;" ::: "memory")

// fast transcendentals via MUFU
__device__ __forceinline__ float ex2f(float x) { float r; asm("ex2.approx.ftz.f32 %0, %1;" : "=f"(r) : "f"(x)); return r; }
__device__ __forceinline__ float rcpf(float x) { float r; asm("rcp.approx.ftz.f32 %0, %1;" : "=f"(r) : "f"(x)); return r; }
__device__ __forceinline__ float sigf(float v)  { return rcpf(1.0f + ex2f(-1.4426950408889634f*v)); }
__device__ __forceinline__ float tanhf_(float v){ return 2.0f*rcpf(1.0f + ex2f(-2.8853900817779268f*v)) - 1.0f; }

// ---------------- device scratch ----------------
__device__ __align__(16) float g_seqT [HH*LDH];
__device__ __align__(16) float g_seq1T[2*HH*LDH];
__device__ __align__(16) float g_y1fT [HH*LDH];
__device__ __align__(16) float g_y1bT [HH*LDH];
__device__ __align__(16) float g_preF [TT*BB*GG];
__device__ __align__(16) float g_preB [TT*BB*GG];
__device__ __align__(16) float g_c0fT [HH*BB];
__device__ __align__(16) float g_c0bT [HH*BB];
__device__ __align__(16) float g_c1fT [HH*BB];
__device__ __align__(16) float g_c1bT [HH*BB];
__device__ __align__(16) float g_zeros[HH*BB];
__device__ __align__(16) float g_z    [BB*LL];
__device__ __align__(16) float g_dh0T [HH*BB];
__device__ __align__(16) float g_dh1T [HH*BB];
__device__ __align__(16) float g_dh1n [BB*HH];
__device__ __align__(16) float g_dc0  [BB*HH];
__device__ __align__(16) float g_dc1T [HH*BB];
__device__ __align__(16) float g_part0 [BB*GG];
__device__ __align__(16) float g_part1a[BB*GG];
__device__ __align__(16) float g_part1b[BB*GG];
__device__ __align__(16) float g_ptab [VV*GG];
__device__ __align__(16) float g_embT [HH*VV];
__device__ __align__(16) float g_wt   [9*1024*1024];
__device__ __align__(16) float g_wt4  [7*1024*1024];

// ---------------- transforms ----------------
__global__ void wt_kernel(const float* __restrict__ in, float* __restrict__ out,
                          int N, int K) {
    int total = N*K;
    for (int i = blockIdx.x*blockDim.x + threadIdx.x; i < total; i += gridDim.x*blockDim.x) {
        int n = i % N; int k = i / N;
        out[i] = in[(size_t)n*K + k];
    }
}
__global__ void wt4_kernel(const float* __restrict__ in, float* __restrict__ out) {
    int total = HH*GG;
    for (int i = blockIdx.x*blockDim.x + threadIdx.x; i < total; i += gridDim.x*blockDim.x) {
        int g = i & 3; int n = (i >> 2) & 511; int k = i >> 11;
        out[i] = in[((size_t)(g*HH + n))*HH + k];
    }
}
__global__ void embT_kernel(const int* __restrict__ x, const float* __restrict__ emb,
                            float* __restrict__ seqT) {
    int total = HH*LDH;
    for (int i = blockIdx.x*blockDim.x + threadIdx.x; i < total; i += gridDim.x*blockDim.x) {
        int k = i / LDH; int m = i % LDH;
        int t = m / BB;  int b = m % BB;
        seqT[i] = emb[x[b*TT + t]*HH + k];
    }
}

// ================= sgemm_ca: 3-buffer single-sync pipeline =================
__global__ __launch_bounds__(256, 2) void sgemm_ca(const float* __restrict__ AT,
                                                   const float* __restrict__ WT,
                                                   const float* __restrict__ bias,
                                                   float* __restrict__ C,
                                                   int M, int N, int K) {
    __shared__ __align__(16) float S[3*4096];   // 3 bufs x (As 2048 + Ws 2048)
    const int bm = blockIdx.y * 128;
    const int bn = blockIdx.x * 128;
    const int tid = threadIdx.x;
    const int tx = tid % 16;
    const int ty = tid / 16;
    const int NS = K / 16;

    const int ck  = tid >> 5;
    const int co  = (tid & 31) * 4;
    const float* asrc = AT + (size_t)ck*M + bm + co;
    const float* wsrc = WT + (size_t)ck*N + bn + co;
    unsigned sb = smem_u32(S);
    unsigned adst = sb + ((ck*128 + co) << 2);
    unsigned wdst = sb + ((2048 + ck*128 + co) << 2);

    #define PRE_ISSUE(s) { unsigned o_ = (unsigned)((s)%3)*16384u; size_t ka_ = (size_t)(s)*16*M, kw_ = (size_t)(s)*16*N; \
        CP16(adst + o_, asrc + ka_); CP16(adst + o_ + 4096u, asrc + ka_ + 8*(size_t)M); \
        CP16(wdst + o_, wsrc + kw_); CP16(wdst + o_ + 4096u, wsrc + kw_ + 8*(size_t)N); CP_COMMIT; }

    u64t acc2[4][8];
    #pragma unroll
    for (int p = 0; p < 4; p++)
        #pragma unroll
        for (int j = 0; j < 8; j++) acc2[p][j] = 0ull;

    PRE_ISSUE(0);
    PRE_ISSUE(1);

    for (int s = 0; s < NS; s++) {
        if (s == NS - 1) { CP_WAIT0; } else { CP_WAIT1; }
        __syncthreads();
        if (s + 2 < NS) PRE_ISSUE(s+2);
        const float* Bq = S + (s % 3)*4096;
        #pragma unroll
        for (int k = 0; k < 16; k++) {
            ulonglong2 A0 = *(const ulonglong2*)&Bq[k*128 + ty*8];
            ulonglong2 A1 = *(const ulonglong2*)&Bq[k*128 + ty*8 + 4];
            u64t apair[4] = {A0.x, A0.y, A1.x, A1.y};
            float w[8];
            *(float4*)&w[0] = *(const float4*)&Bq[2048 + k*128 + tx*8];
            *(float4*)&w[4] = *(const float4*)&Bq[2048 + k*128 + tx*8 + 4];
            #pragma unroll
            for (int j = 0; j < 8; j++) {
                u64t w2 = pack2(w[j], w[j]);
                #pragma unroll
                for (int p = 0; p < 4; p++) fma2(acc2[p][j], apair[p], w2);
            }
        }
    }

    float bb[8];
    *(float4*)&bb[0] = *(const float4*)(bias + bn + tx*8);
    *(float4*)&bb[4] = *(const float4*)(bias + bn + tx*8 + 4);
    #pragma unroll
    for (int p = 0; p < 4; p++) {
        float2 v[8];
        #pragma unroll
        for (int j = 0; j < 8; j++) v[j] = unpack2(acc2[p][j]);
        #pragma unroll
        for (int sub = 0; sub < 2; sub++) {
            size_t row = (size_t)(bm + ty*8 + 2*p + sub)*N + bn + tx*8;
            float o[8];
            #pragma unroll
            for (int j = 0; j < 8; j++) o[j] = (sub ? v[j].y : v[j].x) + bb[j];
            *(float4*)&C[row]     = *(float4*)&o[0];
            *(float4*)&C[row + 4] = *(float4*)&o[4];
        }
    }
    #undef PRE_ISSUE
}

// ====== gate GEMM core: split-K (512 thr), 3-buffer single-sync cp.async pipeline ======
#define GBUF 3072                    // floats per buffer per half (Hs 1024 + Ws 2048)
#define GHALF (3*GBUF)               // 9216 floats per half
#define GSMEM (2*GHALF)              // 18432 floats = 73728 B (dynamic)

template<int NST>
__device__ __forceinline__ void gate_gemm_ca(const float* __restrict__ hT, int lda,
                                             const float* __restrict__ WT4,
                                             int bm, int bn, int kbeg,
                                             float* __restrict__ base,
                                             u64t acc2[4][4]) {
    const int lt = threadIdx.x & 255;
    const int tx = lt & 31;
    const int ty = lt >> 5;

    const float* hsrc = hT + (size_t)(kbeg + (lt >> 4))*lda + bm + (lt & 15)*4;
    const float* wsrc = WT4 + (size_t)(kbeg + (lt >> 5))*GG + (size_t)bn*4 + (lt & 31)*4;
    unsigned sb = smem_u32(base);
    unsigned hdst = sb + (((lt >> 4)*64 + (lt & 15)*4) << 2);
    unsigned wdst = sb + ((1024 + (lt >> 5)*128 + (lt & 31)*4) << 2);

    #define G_ISSUE(s) { unsigned o_ = (unsigned)((s)%3)*(GBUF*4u); size_t kh_ = (size_t)(s)*16*lda, kw_ = (size_t)(s)*16*GG; \
        CP16(hdst + o_, hsrc + kh_); \
        CP16(wdst + o_, wsrc + kw_); CP16(wdst + o_ + 4096u, wsrc + kw_ + 8*(size_t)GG); CP_COMMIT; }

    G_ISSUE(0);
    G_ISSUE(1);

    #pragma unroll 2
    for (int s = 0; s < NST; s++) {
        if (s == NST - 1) { CP_WAIT0; } else { CP_WAIT1; }
        __syncthreads();
        if (s + 2 < NST) G_ISSUE(s+2);
        const float* Bq = base + (s % 3)*GBUF;
        #pragma unroll
        for (int k = 0; k < 16; k++) {
            ulonglong2 A0 = *(const ulonglong2*)&Bq[k*64 + ty*8];
            ulonglong2 A1 = *(const ulonglong2*)&Bq[k*64 + ty*8 + 4];
            float4 wv = *(const float4*)&Bq[1024 + k*128 + tx*4];
            u64t wi  = pack2(wv.x, wv.x);
            u64t wf  = pack2(wv.y, wv.y);
            u64t wg2 = pack2(wv.z, wv.z);
            u64t wo  = pack2(wv.w, wv.w);
            fma2(acc2[0][0], A0.x, wi);  fma2(acc2[0][1], A0.y, wi);
            fma2(acc2[0][2], A1.x, wi);  fma2(acc2[0][3], A1.y, wi);
            fma2(acc2[1][0], A0.x, wf);  fma2(acc2[1][1], A0.y, wf);
            fma2(acc2[1][2], A1.x, wf);  fma2(acc2[1][3], A1.y, wf);
            fma2(acc2[2][0], A0.x, wg2); fma2(acc2[2][1], A0.y, wg2);
            fma2(acc2[2][2], A1.x, wg2); fma2(acc2[2][3], A1.y, wg2);
            fma2(acc2[3][0], A0.x, wo);  fma2(acc2[3][1], A0.y, wo);
            fma2(acc2[3][2], A1.x, wo);  fma2(acc2[3][3], A1.y, wo);
        }
    }
    #undef G_ISSUE
}

__device__ __forceinline__ void ksplit_merge(float* __restrict__ smemAll,
                                             u64t acc2[4][4], int half) {
    u64t* red = reinterpret_cast<u64t*>(smemAll);
    const int lt = threadIdx.x & 255;
    __syncthreads();
    if (half == 1) {
        #pragma unroll
        for (int g = 0; g < 4; g++)
            #pragma unroll
            for (int p = 0; p < 4; p++)
                red[lt*16 + g*4 + p] = acc2[g][p];
    }
    __syncthreads();
    if (half == 0) {
        #pragma unroll
        for (int g = 0; g < 4; g++)
            #pragma unroll
            for (int p = 0; p < 4; p++)
                add2(acc2[g][p], red[lt*16 + g*4 + p]);
    }
}

// Epilogue; pre2 optional second partial buffer.
__device__ __forceinline__ void lstm_epiT(u64t acc2[4][4],
                                          const float* __restrict__ pre,
                                          const float* __restrict__ pre2,
                                          const float* __restrict__ cinT,
                                          float* __restrict__ coutT,
                                          float* __restrict__ houtT, int ldh,
                                          float* __restrict__ houtN,
                                          int bm, int bn) {
    const int lt = threadIdx.x & 255;
    const int tx = lt & 31;
    const int ty = lt >> 5;
    const int n  = bn + tx;
    const int b0 = bm + ty*8;
    float cv[8], hv[8], co[8];
    *(float4*)&cv[0] = *(const float4*)&cinT[(size_t)n*BB + b0];
    *(float4*)&cv[4] = *(const float4*)&cinT[(size_t)n*BB + b0 + 4];
    #pragma unroll
    for (int p = 0; p < 4; p++) {
        float2 vi = unpack2(acc2[0][p]);
        float2 vf = unpack2(acc2[1][p]);
        float2 vg = unpack2(acc2[2][p]);
        float2 vo = unpack2(acc2[3][p]);
        #pragma unroll
        for (int sub = 0; sub < 2; sub++) {
            int idx = 2*p + sub;
            int b = b0 + idx;
            const float* pb = pre + (size_t)b*GG;
            float gi = pb[0*HH + n] + (sub ? vi.y : vi.x);
            float gf = pb[1*HH + n] + (sub ? vf.y : vf.x);
            float gg = pb[2*HH + n] + (sub ? vg.y : vg.x);
            float go = pb[3*HH + n] + (sub ? vo.y : vo.x);
            if (pre2) {
                const float* pc = pre2 + (size_t)b*GG;
                gi += pc[0*HH + n]; gf += pc[1*HH + n];
                gg += pc[2*HH + n]; go += pc[3*HH + n];
            }
            float cn = sigf(gf)*cv[idx] + sigf(gi)*tanhf_(gg);
            co[idx] = cn;
            hv[idx] = sigf(go)*tanhf_(cn);
        }
    }
    *(float4*)&coutT[(size_t)n*BB + b0]     = *(float4*)&co[0];
    *(float4*)&coutT[(size_t)n*BB + b0 + 4] = *(float4*)&co[4];
    *(float4*)&houtT[(size_t)n*ldh + b0]     = *(float4*)&hv[0];
    *(float4*)&houtT[(size_t)n*ldh + b0 + 4] = *(float4*)&hv[4];
    if (houtN) {
        #pragma unroll
        for (int i = 0; i < 8; i++) houtN[(size_t)(b0+i)*HH + n] = hv[i];
    }
}

__device__ __forceinline__ void part_store(u64t acc2[4][4],
                                           const float* __restrict__ bias,
                                           float* __restrict__ outp,
                                           int bm, int bn) {
    const int lt = threadIdx.x & 255;
    const int tx = lt & 31;
    const int ty = lt >> 5;
    const int n = bn + tx;
    #pragma unroll
    for (int g = 0; g < 4; g++) {
        float bv = bias[g*HH + n];
        #pragma unroll
        for (int p = 0; p < 4; p++) {
            float2 v = unpack2(acc2[g][p]);
            int b0 = bm + ty*8 + 2*p;
            outp[(size_t)(b0+0)*GG + g*HH + n] = v.x + bv;
            outp[(size_t)(b0+1)*GG + g*HH + n] = v.y + bv;
        }
    }
}

#define ZERO_ACC(a) { _Pragma("unroll") for (int g_=0; g_<4; g_++) { \
    _Pragma("unroll") for (int p_=0; p_<4; p_++) (a)[g_][p_] = 0ull; } }

// ---------------- encoder recurrent step ----------------
struct DirT {
    const float* pre;
    const float* hinT; int lda;
    const float* cinT;
    float* coutT;
    float* houtT;
    const float* WT4;
};

__global__ __launch_bounds__(512, 1) void lstm_stepT(DirT A0, DirT A1) {
    extern __shared__ __align__(16) float S[];
    DirT d = blockIdx.z ? A1 : A0;
    const int half = threadIdx.x >> 8;
    float* base = S + half*GHALF;
    int bm = blockIdx.y * 64;
    int bn = blockIdx.x * 32;
    u64t acc2[4][4];
    ZERO_ACC(acc2);
    gate_gemm_ca<16>(d.hinT, d.lda, d.WT4, bm, bn, half*256, base, acc2);
    ksplit_merge(S, acc2, half);
    if (half == 0)
        lstm_epiT(acc2, d.pre, nullptr, d.cinT, d.coutT, d.houtT, LDH, nullptr, bm, bn);
}

// ---------------- decoder phase Y: cell1 (z=0) || part0' (z=1) ----------------
__global__ __launch_bounds__(512, 1) void dec_Y(const float* __restrict__ dh0T,
                                                const float* __restrict__ w4ih1,
                                                const float* __restrict__ part1a,
                                                const float* __restrict__ part1b,
                                                float* __restrict__ dc1T,
                                                float* __restrict__ dh1T,
                                                float* __restrict__ dh1n,
                                                const float* __restrict__ w4hh0,
                                                const float* __restrict__ zerob,
                                                float* __restrict__ part0) {
    extern __shared__ __align__(16) float S[];
    const int half = threadIdx.x >> 8;
    float* base = S + half*GHALF;
    int bm = blockIdx.y * 64;
    int bn = blockIdx.x * 32;
    u64t acc2[4][4];
    ZERO_ACC(acc2);
    if (blockIdx.z == 0) {
        gate_gemm_ca<16>(dh0T, BB, w4ih1, bm, bn, half*256, base, acc2);
        ksplit_merge(S, acc2, half);
        if (half == 0) lstm_epiT(acc2, part1a, part1b, dc1T, dc1T, dh1T, BB, dh1n, bm, bn);
    } else {
        gate_gemm_ca<16>(dh0T, BB, w4hh0, bm, bn, half*256, base, acc2);
        ksplit_merge(S, acc2, half);
        if (half == 0) part_store(acc2, zerob, part0, bm, bn);
    }
}

// ---- phase Z: logits+argmax+cell0 (z=0) || part1a (z=1) || part1b (z=2) -----
__global__ __launch_bounds__(512, 1) void dec_Z(const float* __restrict__ dh1T,
                                                const float* __restrict__ dh1n,
                                                const float* __restrict__ Wout,
                                                const float* __restrict__ bout,
                                                const float* __restrict__ w4hh1,
                                                const float* __restrict__ b1,
                                                const float* __restrict__ zerob,
                                                float* __restrict__ part1a,
                                                float* __restrict__ part1b,
                                                const float* __restrict__ Ptab,
                                                const float* __restrict__ part0,
                                                float* __restrict__ dc0,
                                                float* __restrict__ dh0T,
                                                float* __restrict__ recon,
                                                int t) {
    extern __shared__ __align__(16) float S[];
    if (blockIdx.z >= 1) {
        const int half = threadIdx.x >> 8;
        float* base = S + half*GHALF;
        int bm = blockIdx.y * 64;
        int bn = blockIdx.x * 32;
        int kb = (blockIdx.z - 1) * 256 + half*128;
        u64t acc2[4][4];
        ZERO_ACC(acc2);
        gate_gemm_ca<8>(dh1T, BB, w4hh1, bm, bn, kb, base, acc2);
        ksplit_merge(S, acc2, half);
        if (half == 0) {
            if (blockIdx.z == 1) part_store(acc2, b1,    part1a, bm, bn);
            else                 part_store(acc2, zerob, part1b, bm, bn);
        }
        return;
    }
    const int tid = threadIdx.x;
    const int bid = blockIdx.y*16 + blockIdx.x;
    const int b0r = bid * 4;
    float* sh = S;
    float* sv = S + 4*HH;
    int*   si = (int*)(S + 4*HH + 4*VV);
    ((float4*)sh)[tid] = ((const float4*)(dh1n + (size_t)b0r*HH))[tid];
    __syncthreads();
    const int v = tid & 127;
    const int r = tid >> 7;
    const float4* w4 = (const float4*)(Wout + (size_t)v*HH);
    const float* shr = sh + r*HH;
    float acc = bout[v];
    #pragma unroll 8
    for (int k = 0; k < HH/4; k++) {
        float4 wv = w4[k];
        float4 s4 = *(const float4*)&shr[k*4];
        acc += s4.x*wv.x + s4.y*wv.y + s4.z*wv.z + s4.w*wv.w;
    }
    recon[(size_t)(b0r+r)*TT*VV + (size_t)t*VV + v] = acc;
    sv[r*VV + v] = acc;
    si[r*VV + v] = v;
    __syncthreads();
    for (int s2 = 64; s2 > 0; s2 >>= 1) {
        if (v < s2) {
            float ov = sv[r*VV + v + s2]; int oi = si[r*VV + v + s2];
            if (ov > sv[r*VV + v] || (ov == sv[r*VV + v] && oi < si[r*VV + v])) {
                sv[r*VV + v] = ov; si[r*VV + v] = oi;
            }
        }
        __syncthreads();
    }
    const int tk = si[r*VV];
    const int b = b0r + r;
    const int h0c = v * 4;
    const float* pt = Ptab + (size_t)tk*GG;
    const float* p0 = part0 + (size_t)b*GG;
    float4 pi = *(const float4*)&pt[0*HH + h0c]; float4 qi = *(const float4*)&p0[0*HH + h0c];
    float4 pf = *(const float4*)&pt[1*HH + h0c]; float4 qf = *(const float4*)&p0[1*HH + h0c];
    float4 pg = *(const float4*)&pt[2*HH + h0c]; float4 qg = *(const float4*)&p0[2*HH + h0c];
    float4 po = *(const float4*)&pt[3*HH + h0c]; float4 qo = *(const float4*)&p0[3*HH + h0c];
    float4 c4 = *(const float4*)&dc0[(size_t)b*HH + h0c];
    float gi[4] = {pi.x+qi.x, pi.y+qi.y, pi.z+qi.z, pi.w+qi.w};
    float gf[4] = {pf.x+qf.x, pf.y+qf.y, pf.z+qf.z, pf.w+qf.w};
    float gg[4] = {pg.x+qg.x, pg.y+qg.y, pg.z+qg.z, pg.w+qg.w};
    float go[4] = {po.x+qo.x, po.y+qo.y, po.z+qo.z, po.w+qo.w};
    float cc[4] = {c4.x, c4.y, c4.z, c4.w};
    float co[4];
    #pragma unroll
    for (int j = 0; j < 4; j++) {
        float cn = sigf(gf[j])*cc[j] + sigf(gi[j])*tanhf_(gg[j]);
        co[j] = cn;
        dh0T[(size_t)(h0c+j)*BB + b] = sigf(go[j])*tanhf_(cn);
    }
    *(float4*)&dc0[(size_t)b*HH + h0c] = make_float4(co[0], co[1], co[2], co[3]);
}

// ---------------- cell0 at t=0 ----------------
__global__ __launch_bounds__(128) void cell0_init_kernel(const float* __restrict__ Ptab,
                                                         const float* __restrict__ part0,
                                                         float* __restrict__ dc0,
                                                         float* __restrict__ dh0T) {
    const int b = blockIdx.x;
    const int h0c = threadIdx.x * 4;
    const float* pt = Ptab + (size_t)1*GG;
    const float* p0 = part0 + (size_t)b*GG;
    float4 pi = *(const float4*)&pt[0*HH + h0c]; float4 qi = *(const float4*)&p0[0*HH + h0c];
    float4 pf = *(const float4*)&pt[1*HH + h0c]; float4 qf = *(const float4*)&p0[1*HH + h0c];
    float4 pg = *(const float4*)&pt[2*HH + h0c]; float4 qg = *(const float4*)&p0[2*HH + h0c];
    float4 po = *(const float4*)&pt[3*HH + h0c]; float4 qo = *(const float4*)&p0[3*HH + h0c];
    float4 c4 = *(const float4*)&dc0[(size_t)b*HH + h0c];
    float gi[4] = {pi.x+qi.x, pi.y+qi.y, pi.z+qi.z, pi.w+qi.w};
    float gf[4] = {pf.x+qf.x, pf.y+qf.y, pf.z+qf.z, pf.w+qf.w};
    float gg[4] = {pg.x+qg.x, pg.y+qg.y, pg.z+qg.z, pg.w+qg.w};
    float go[4] = {po.x+qo.x, po.y+qo.y, po.z+qo.z, po.w+qo.w};
    float cc[4] = {c4.x, c4.y, c4.z, c4.w};
    float co[4];
    #pragma unroll
    for (int j = 0; j < 4; j++) {
        float cn = sigf(gf[j])*cc[j] + sigf(gi[j])*tanhf_(gg[j]);
        co[j] = cn;
        dh0T[(size_t)(h0c+j)*BB + b] = sigf(go[j])*tanhf_(cn);
    }
    *(float4*)&dc0[(size_t)b*HH + h0c] = make_float4(co[0], co[1], co[2], co[3]);
}

// ---------------- mu/logvar heads ----------------
__global__ __launch_bounds__(256) void head_kernel(const float* __restrict__ hfT,
                                                   const float* __restrict__ hbT,
                                                   const float* __restrict__ Wmu,
                                                   const float* __restrict__ bmu,
                                                   const float* __restrict__ Wlv,
                                                   const float* __restrict__ blv,
                                                   float* __restrict__ out_mu,
                                                   float* __restrict__ out_lv,
                                                   float* __restrict__ zbuf) {
    int b = blockIdx.x;
    int tid = threadIdx.x;
    __shared__ float sh[2*HH];
    for (int i = tid; i < HH; i += 256) {
        sh[i]      = hfT[(size_t)i*LDH + b];
        sh[HH + i] = hbT[(size_t)i*LDH + b];
    }
    __syncthreads();
    const float* W;
    float acc;
    int l;
    if (tid < LL) { l = tid;      W = Wmu + (size_t)l*2*HH; acc = bmu[l]; }
    else          { l = tid - LL; W = Wlv + (size_t)l*2*HH; acc = blv[l]; }
    #pragma unroll 8
    for (int k = 0; k < 2*HH; k++) acc += sh[k]*W[k];
    if (tid < LL) { out_mu[b*LL + l] = acc; zbuf[b*LL + l] = acc; }
    else          { out_lv[b*LL + l] = acc; }
}

// ---------------- decoder init ----------------
__global__ __launch_bounds__(512) void dec_init_kernel(const float* __restrict__ z,
                                                       const float* __restrict__ W,
                                                       const float* __restrict__ bias,
                                                       float* __restrict__ h0T,
                                                       float* __restrict__ h1T,
                                                       float* __restrict__ h1n,
                                                       float* __restrict__ c0n,
                                                       float* __restrict__ c1T) {
    int b = blockIdx.x;
    int tid = threadIdx.x;
    __shared__ float sz[LL];
    if (tid < LL) sz[tid] = z[b*LL + tid];
    __syncthreads();
    float acc = bias[tid];
    const float* w = W + (size_t)tid*LL;
    #pragma unroll 8
    for (int k = 0; k < LL; k++) acc += sz[k]*w[k];
    h0T[(size_t)tid*BB + b] = acc;
    h1T[(size_t)tid*BB + b] = acc;
    h1n[(size_t)b*HH + tid] = acc;
    c0n[(size_t)b*HH + tid] = 0.0f;
    c1T[(size_t)tid*BB + b] = 0.0f;
}

// =================================== host launcher ====================================
extern "C" void kernel_launch(void* const* d_in, const int* in_sizes, int n_in,
                              void* d_out, int out_size) {
    const int*   x           = (const int*)  d_in[0];
    const float* emb         = (const float*)d_in[1];
    const float* enc_wih_l0  = (const float*)d_in[2];
    const float* enc_whh_l0  = (const float*)d_in[3];
    const float* enc_b_l0    = (const float*)d_in[4];
    const float* enc_wih_l1  = (const float*)d_in[5];
    const float* enc_whh_l1  = (const float*)d_in[6];
    const float* enc_b_l1    = (const float*)d_in[7];
    const float* fc_mu_w     = (const float*)d_in[8];
    const float* fc_mu_b     = (const float*)d_in[9];
    const float* fc_lv_w     = (const float*)d_in[10];
    const float* fc_lv_b     = (const float*)d_in[11];
    const float* dec_in_w    = (const float*)d_in[12];
    const float* dec_in_b    = (const float*)d_in[13];
    const float* dec_wih     = (const float*)d_in[14];
    const float* dec_whh     = (const float*)d_in[15];
    const float* dec_b       = (const float*)d_in[16];
    const float* dec_out_w   = (const float*)d_in[17];
    const float* dec_out_b   = (const float*)d_in[18];

    float* out       = (float*)d_out;
    float* out_recon = out;
    float* out_mu    = out + (size_t)BB*TT*VV;
    float* out_lv    = out_mu + (size_t)BB*LL;

    float *seqT, *seq1T, *y1fT, *y1bT, *preF, *preB;
    float *c0fT, *c0bT, *c1fT, *c1bT, *zeros, *zbuf;
    float *dh0T, *dh1T, *dh1n, *dc0, *dc1T, *part0, *part1a, *part1b, *ptab, *embT, *wt, *wt4;
    cudaGetSymbolAddress((void**)&seqT,  g_seqT);
    cudaGetSymbolAddress((void**)&seq1T, g_seq1T);
    cudaGetSymbolAddress((void**)&y1fT,  g_y1fT);
    cudaGetSymbolAddress((void**)&y1bT,  g_y1bT);
    cudaGetSymbolAddress((void**)&preF,  g_preF);
    cudaGetSymbolAddress((void**)&preB,  g_preB);
    cudaGetSymbolAddress((void**)&c0fT,  g_c0fT);
    cudaGetSymbolAddress((void**)&c0bT,  g_c0bT);
    cudaGetSymbolAddress((void**)&c1fT,  g_c1fT);
    cudaGetSymbolAddress((void**)&c1bT,  g_c1bT);
    cudaGetSymbolAddress((void**)&zeros, g_zeros);
    cudaGetSymbolAddress((void**)&zbuf,  g_z);
    cudaGetSymbolAddress((void**)&dh0T,  g_dh0T);
    cudaGetSymbolAddress((void**)&dh1T,  g_dh1T);
    cudaGetSymbolAddress((void**)&dh1n,  g_dh1n);
    cudaGetSymbolAddress((void**)&dc0,   g_dc0);
    cudaGetSymbolAddress((void**)&dc1T,  g_dc1T);
    cudaGetSymbolAddress((void**)&part0, g_part0);
    cudaGetSymbolAddress((void**)&part1a,g_part1a);
    cudaGetSymbolAddress((void**)&part1b,g_part1b);
    cudaGetSymbolAddress((void**)&ptab,  g_ptab);
    cudaGetSymbolAddress((void**)&embT,  g_embT);
    cudaGetSymbolAddress((void**)&wt,    g_wt);
    cudaGetSymbolAddress((void**)&wt4,   g_wt4);

    const size_t M1 = 1024*1024;
    float* wtA0f = wt;
    float* wtA0b = wt + 1*M1;
    float* wtA1f = wt + 2*M1;
    float* wtA1b = wt + 4*M1;
    float* wtPt  = wt + 6*M1;
    float* wtD0  = wt + 7*M1;
    float* wtD1  = wt + 8*M1;
    float* w4e0f = wt4;
    float* w4e0b = wt4 + 1*M1;
    float* w4e1f = wt4 + 2*M1;
    float* w4e1b = wt4 + 3*M1;
    float* w4ih1 = wt4 + 4*M1;
    float* w4hh0 = wt4 + 5*M1;
    float* w4hh1 = wt4 + 6*M1;

    const float* dWih0 = dec_wih;
    const float* dWih1 = dec_wih + (size_t)GG*HH;
    const float* dWhh0 = dec_whh;
    const float* dWhh1 = dec_whh + (size_t)GG*HH;
    const float* db0   = dec_b;
    const float* db1   = dec_b + GG;

    // dynamic smem opt-in (idempotent host-side calls; legal during capture)
    const int GB = GSMEM * 4;   // 73728 bytes
    cudaFuncSetAttribute(lstm_stepT, cudaFuncAttributeMaxDynamicSharedMemorySize, GB);
    cudaFuncSetAttribute(dec_Y,      cudaFuncAttributeMaxDynamicSharedMemorySize, GB);
    cudaFuncSetAttribute(dec_Z,      cudaFuncAttributeMaxDynamicSharedMemorySize, GB);

    // ---- transforms ----
    embT_kernel<<<2048, 256>>>(x, emb, seqT);
    wt_kernel<<<512, 256>>>(emb, embT, VV, HH);
    wt_kernel<<<1024, 256>>>(enc_wih_l0,                 wtA0f, GG, HH);
    wt_kernel<<<1024, 256>>>(enc_wih_l0 + (size_t)GG*HH, wtA0b, GG, HH);
    wt_kernel<<<2048, 256>>>(enc_wih_l1,                    wtA1f, GG, 2*HH);
    wt_kernel<<<2048, 256>>>(enc_wih_l1 + (size_t)GG*2*HH,  wtA1b, GG, 2*HH);
    wt_kernel<<<1024, 256>>>(dWih0, wtPt, GG, HH);
    wt_kernel<<<1024, 256>>>(dWhh0, wtD0, GG, HH);
    wt_kernel<<<1024, 256>>>(dWhh1, wtD1, GG, HH);
    wt4_kernel<<<1024, 256>>>(enc_whh_l0,                 w4e0f);
    wt4_kernel<<<1024, 256>>>(enc_whh_l0 + (size_t)GG*HH, w4e0b);
    wt4_kernel<<<1024, 256>>>(enc_whh_l1,                 w4e1f);
    wt4_kernel<<<1024, 256>>>(enc_whh_l1 + (size_t)GG*HH, w4e1b);
    wt4_kernel<<<1024, 256>>>(dWih1, w4ih1);
    wt4_kernel<<<1024, 256>>>(dWhh0, w4hh0);
    wt4_kernel<<<1024, 256>>>(dWhh1, w4hh1);

    // ---- Ptab ----
    sgemm_ca<<<dim3(GG/128, VV/128), 256>>>(embT, wtPt, db0, ptab, VV, GG, HH);

    // ---- encoder layer 0 ----
    dim3 preGrd(GG/128, LDH/128);
    sgemm_ca<<<preGrd, 256>>>(seqT, wtA0f, enc_b_l0,      preF, LDH, GG, HH);
    sgemm_ca<<<preGrd, 256>>>(seqT, wtA0b, enc_b_l0 + GG, preB, LDH, GG, HH);

    dim3 stepGrd(HH/32, BB/64, 2);
    float* seq1Tb = seq1T + (size_t)HH*LDH;
    for (int s = 0; s < TT; s++) {
        int tf = s, tb = TT-1-s;
        DirT df = { preF + (size_t)tf*BB*GG,
                    s ? seq1T + (size_t)(tf-1)*BB : zeros, s ? LDH : BB,
                    s ? c0fT : zeros, c0fT,
                    seq1T + (size_t)tf*BB, w4e0f };
        DirT db = { preB + (size_t)tb*BB*GG,
                    s ? seq1Tb + (size_t)(tb+1)*BB : zeros, s ? LDH : BB,
                    s ? c0bT : zeros, c0bT,
                    seq1Tb + (size_t)tb*BB, w4e0b };
        lstm_stepT<<<stepGrd, 512, GB>>>(df, db);
    }

    // ---- encoder layer 1 ----
    sgemm_ca<<<preGrd, 256>>>(seq1T, wtA1f, enc_b_l1,      preF, LDH, GG, 2*HH);
    sgemm_ca<<<preGrd, 256>>>(seq1T, wtA1b, enc_b_l1 + GG, preB, LDH, GG, 2*HH);
    for (int s = 0; s < TT; s++) {
        int tf = s, tb = TT-1-s;
        DirT df = { preF + (size_t)tf*BB*GG,
                    s ? y1fT + (size_t)(tf-1)*BB : zeros, s ? LDH : BB,
                    s ? c1fT : zeros, c1fT,
                    y1fT + (size_t)tf*BB, w4e1f };
        DirT db = { preB + (size_t)tb*BB*GG,
                    s ? y1bT + (size_t)(tb+1)*BB : zeros, s ? LDH : BB,
                    s ? c1bT : zeros, c1bT,
                    y1bT + (size_t)tb*BB, w4e1b };
        lstm_stepT<<<stepGrd, 512, GB>>>(df, db);
    }

    // ---- heads ----
    head_kernel<<<BB, 256>>>(y1fT + (size_t)(TT-1)*BB, y1bT,
                             fc_mu_w, fc_mu_b, fc_lv_w, fc_lv_b,
                             out_mu, out_lv, zbuf);

    // ---- decoder init ----
    dec_init_kernel<<<BB, 512>>>(zbuf, dec_in_w, dec_in_b, dh0T, dh1T, dh1n, dc0, dc1T);
    dim3 partGrd(GG/128, BB/128);
    sgemm_ca<<<partGrd, 256>>>(dh0T, wtD0, zeros, part0,  BB, GG, HH);
    sgemm_ca<<<partGrd, 256>>>(dh1T, wtD1, db1,   part1a, BB, GG, HH);
    cudaMemsetAsync(part1b, 0, (size_t)BB*GG*sizeof(float));
    cell0_init_kernel<<<BB, 128>>>(ptab, part0, dc0, dh0T);

    // ---- autoregressive decode ----
    dim3 yGrd(HH/32, BB/64, 2);
    dim3 zGrd(HH/32, BB/64, 3);
    for (int t = 0; t < TT; t++) {
        dec_Y<<<yGrd, 512, GB>>>(dh0T, w4ih1, part1a, part1b, dc1T, dh1T, dh1n,
                                 w4hh0, zeros, part0);
        dec_Z<<<zGrd, 512, GB>>>(dh1T, dh1n, dec_out_w, dec_out_b, w4hh1, db1, zeros,
                                 part1a, part1b, ptab, part0, dc0, dh0T, out_recon, t);
    }
}

// round 11
// speedup vs baseline: 1.0005x; 1.0005x over previous
#include <cuda_runtime.h>
#include <math.h>

// ---------------- problem constants ----------------
#define TT 128
#define BB 256
#define HH 512
#define GG 2048
#define VV 128
#define LL 128
#define LDH (TT*BB)

typedef unsigned long long u64t;

__device__ __forceinline__ u64t pack2(float x, float y) {
    u64t r; asm("mov.b64 %0, {%1, %2};" : "=l"(r) : "f"(x), "f"(y)); return r;
}
__device__ __forceinline__ void fma2(u64t& d, u64t a, u64t b) {
    asm("fma.rn.f32x2 %0, %1, %2, %0;" : "+l"(d) : "l"(a), "l"(b));
}
__device__ __forceinline__ void add2(u64t& d, u64t a) {
    asm("add.rn.f32x2 %0, %0, %1;" : "+l"(d) : "l"(a));
}
__device__ __forceinline__ float2 unpack2(u64t v) {
    float2 r; asm("mov.b64 {%0, %1}, %2;" : "=f"(r.x), "=f"(r.y) : "l"(v)); return r;
}
__device__ __forceinline__ unsigned smem_u32(const void* p) {
    return (unsigned)__cvta_generic_to_shared(p);
}
#define CP16(dst, src) asm volatile("cp.async.ca.shared.global [%0], [%1], 16;" :: "r"(dst), "l"((const void*)(src)) : "memory")
#define CP_COMMIT      asm volatile("cp.async.commit_group;" ::: "memory")
#define CP_WAIT1       asm volatile("cp.async.wait_group 1;" ::: "memory")
#define CP_WAIT0       asm volatile("cp.async.wait_group 0;" ::: "memory")

// fast transcendentals via MUFU
__device__ __forceinline__ float ex2f(float x) { float r; asm("ex2.approx.ftz.f32 %0, %1;" : "=f"(r) : "f"(x)); return r; }
__device__ __forceinline__ float rcpf(float x) { float r; asm("rcp.approx.ftz.f32 %0, %1;" : "=f"(r) : "f"(x)); return r; }
__device__ __forceinline__ float sigf(float v)  { return rcpf(1.0f + ex2f(-1.4426950408889634f*v)); }
__device__ __forceinline__ float tanhf_(float v){ return 2.0f*rcpf(1.0f + ex2f(-2.8853900817779268f*v)) - 1.0f; }

// ---------------- device scratch ----------------
__device__ __align__(16) float g_seqT [HH*LDH];
__device__ __align__(16) float g_seq1T[2*HH*LDH];
__device__ __align__(16) float g_y1fT [HH*LDH];
__device__ __align__(16) float g_y1bT [HH*LDH];
__device__ __align__(16) float g_preF [TT*BB*GG];
__device__ __align__(16) float g_preB [TT*BB*GG];
__device__ __align__(16) float g_c0fT [HH*BB];
__device__ __align__(16) float g_c0bT [HH*BB];
__device__ __align__(16) float g_c1fT [HH*BB];
__device__ __align__(16) float g_c1bT [HH*BB];
__device__ __align__(16) float g_zeros[HH*BB];
__device__ __align__(16) float g_z    [BB*LL];
__device__ __align__(16) float g_dh0T [HH*BB];
__device__ __align__(16) float g_dh1T [HH*BB];
__device__ __align__(16) float g_dh1n [BB*HH];
__device__ __align__(16) float g_dc0  [BB*HH];
__device__ __align__(16) float g_dc1T [HH*BB];
__device__ __align__(16) float g_part0 [BB*GG];
__device__ __align__(16) float g_part1a[BB*GG];
__device__ __align__(16) float g_part1b[BB*GG];
__device__ __align__(16) float g_ptab [VV*GG];
__device__ __align__(16) float g_embT [HH*VV];
__device__ __align__(16) float g_wt   [9*1024*1024];
__device__ __align__(16) float g_wt4  [7*1024*1024];

// ---------------- transforms ----------------
__global__ void wt_kernel(const float* __restrict__ in, float* __restrict__ out,
                          int N, int K) {
    int total = N*K;
    for (int i = blockIdx.x*blockDim.x + threadIdx.x; i < total; i += gridDim.x*blockDim.x) {
        int n = i % N; int k = i / N;
        out[i] = in[(size_t)n*K + k];
    }
}
__global__ void wt4_kernel(const float* __restrict__ in, float* __restrict__ out) {
    int total = HH*GG;
    for (int i = blockIdx.x*blockDim.x + threadIdx.x; i < total; i += gridDim.x*blockDim.x) {
        int g = i & 3; int n = (i >> 2) & 511; int k = i >> 11;
        out[i] = in[((size_t)(g*HH + n))*HH + k];
    }
}
__global__ void embT_kernel(const int* __restrict__ x, const float* __restrict__ emb,
                            float* __restrict__ seqT) {
    int total = HH*LDH;
    for (int i = blockIdx.x*blockDim.x + threadIdx.x; i < total; i += gridDim.x*blockDim.x) {
        int k = i / LDH; int m = i % LDH;
        int t = m / BB;  int b = m % BB;
        seqT[i] = emb[x[b*TT + t]*HH + k];
    }
}

// ================= sgemm_ca: 3-buffer single-sync pipeline =================
__global__ __launch_bounds__(256, 2) void sgemm_ca(const float* __restrict__ AT,
                                                   const float* __restrict__ WT,
                                                   const float* __restrict__ bias,
                                                   float* __restrict__ C,
                                                   int M, int N, int K) {
    __shared__ __align__(16) float S[3*4096];   // 3 bufs x (As 2048 + Ws 2048)
    const int bm = blockIdx.y * 128;
    const int bn = blockIdx.x * 128;
    const int tid = threadIdx.x;
    const int tx = tid % 16;
    const int ty = tid / 16;
    const int NS = K / 16;

    const int ck  = tid >> 5;
    const int co  = (tid & 31) * 4;
    const float* asrc = AT + (size_t)ck*M + bm + co;
    const float* wsrc = WT + (size_t)ck*N + bn + co;
    unsigned sb = smem_u32(S);
    unsigned adst = sb + ((ck*128 + co) << 2);
    unsigned wdst = sb + ((2048 + ck*128 + co) << 2);

    #define PRE_ISSUE(s) { unsigned o_ = (unsigned)((s)%3)*16384u; size_t ka_ = (size_t)(s)*16*M, kw_ = (size_t)(s)*16*N; \
        CP16(adst + o_, asrc + ka_); CP16(adst + o_ + 4096u, asrc + ka_ + 8*(size_t)M); \
        CP16(wdst + o_, wsrc + kw_); CP16(wdst + o_ + 4096u, wsrc + kw_ + 8*(size_t)N); CP_COMMIT; }

    u64t acc2[4][8];
    #pragma unroll
    for (int p = 0; p < 4; p++)
        #pragma unroll
        for (int j = 0; j < 8; j++) acc2[p][j] = 0ull;

    PRE_ISSUE(0);
    PRE_ISSUE(1);

    for (int s = 0; s < NS; s++) {
        if (s == NS - 1) { CP_WAIT0; } else { CP_WAIT1; }
        __syncthreads();
        if (s + 2 < NS) PRE_ISSUE(s+2);
        const float* Bq = S + (s % 3)*4096;
        #pragma unroll
        for (int k = 0; k < 16; k++) {
            ulonglong2 A0 = *(const ulonglong2*)&Bq[k*128 + ty*8];
            ulonglong2 A1 = *(const ulonglong2*)&Bq[k*128 + ty*8 + 4];
            u64t apair[4] = {A0.x, A0.y, A1.x, A1.y};
            float w[8];
            *(float4*)&w[0] = *(const float4*)&Bq[2048 + k*128 + tx*8];
            *(float4*)&w[4] = *(const float4*)&Bq[2048 + k*128 + tx*8 + 4];
            #pragma unroll
            for (int j = 0; j < 8; j++) {
                u64t w2 = pack2(w[j], w[j]);
                #pragma unroll
                for (int p = 0; p < 4; p++) fma2(acc2[p][j], apair[p], w2);
            }
        }
    }

    float bb[8];
    *(float4*)&bb[0] = *(const float4*)(bias + bn + tx*8);
    *(float4*)&bb[4] = *(const float4*)(bias + bn + tx*8 + 4);
    #pragma unroll
    for (int p = 0; p < 4; p++) {
        float2 v[8];
        #pragma unroll
        for (int j = 0; j < 8; j++) v[j] = unpack2(acc2[p][j]);
        #pragma unroll
        for (int sub = 0; sub < 2; sub++) {
            size_t row = (size_t)(bm + ty*8 + 2*p + sub)*N + bn + tx*8;
            float o[8];
            #pragma unroll
            for (int j = 0; j < 8; j++) o[j] = (sub ? v[j].y : v[j].x) + bb[j];
            *(float4*)&C[row]     = *(float4*)&o[0];
            *(float4*)&C[row + 4] = *(float4*)&o[4];
        }
    }
    #undef PRE_ISSUE
}

// ====== gate GEMM core: split-K (512 thr), 3-buffer single-sync cp.async pipeline ======
#define GBUF 3072                    // floats per buffer per half (Hs 1024 + Ws 2048)
#define GHALF (3*GBUF)               // 9216 floats per half
#define GSMEM (2*GHALF)              // 18432 floats = 73728 B (dynamic)

template<int NST>
__device__ __forceinline__ void gate_gemm_ca(const float* __restrict__ hT, int lda,
                                             const float* __restrict__ WT4,
                                             int bm, int bn, int kbeg,
                                             float* __restrict__ base,
                                             u64t acc2[4][4]) {
    const int lt = threadIdx.x & 255;
    const int tx = lt & 31;
    const int ty = lt >> 5;

    const float* hsrc = hT + (size_t)(kbeg + (lt >> 4))*lda + bm + (lt & 15)*4;
    const float* wsrc = WT4 + (size_t)(kbeg + (lt >> 5))*GG + (size_t)bn*4 + (lt & 31)*4;
    unsigned sb = smem_u32(base);
    unsigned hdst = sb + (((lt >> 4)*64 + (lt & 15)*4) << 2);
    unsigned wdst = sb + ((1024 + (lt >> 5)*128 + (lt & 31)*4) << 2);

    #define G_ISSUE(s) { unsigned o_ = (unsigned)((s)%3)*(GBUF*4u); size_t kh_ = (size_t)(s)*16*lda, kw_ = (size_t)(s)*16*GG; \
        CP16(hdst + o_, hsrc + kh_); \
        CP16(wdst + o_, wsrc + kw_); CP16(wdst + o_ + 4096u, wsrc + kw_ + 8*(size_t)GG); CP_COMMIT; }

    G_ISSUE(0);
    G_ISSUE(1);

    #pragma unroll 2
    for (int s = 0; s < NST; s++) {
        if (s == NST - 1) { CP_WAIT0; } else { CP_WAIT1; }
        __syncthreads();
        if (s + 2 < NST) G_ISSUE(s+2);
        const float* Bq = base + (s % 3)*GBUF;
        #pragma unroll
        for (int k = 0; k < 16; k++) {
            ulonglong2 A0 = *(const ulonglong2*)&Bq[k*64 + ty*8];
            ulonglong2 A1 = *(const ulonglong2*)&Bq[k*64 + ty*8 + 4];
            float4 wv = *(const float4*)&Bq[1024 + k*128 + tx*4];
            u64t wi  = pack2(wv.x, wv.x);
            u64t wf  = pack2(wv.y, wv.y);
            u64t wg2 = pack2(wv.z, wv.z);
            u64t wo  = pack2(wv.w, wv.w);
            fma2(acc2[0][0], A0.x, wi);  fma2(acc2[0][1], A0.y, wi);
            fma2(acc2[0][2], A1.x, wi);  fma2(acc2[0][3], A1.y, wi);
            fma2(acc2[1][0], A0.x, wf);  fma2(acc2[1][1], A0.y, wf);
            fma2(acc2[1][2], A1.x, wf);  fma2(acc2[1][3], A1.y, wf);
            fma2(acc2[2][0], A0.x, wg2); fma2(acc2[2][1], A0.y, wg2);
            fma2(acc2[2][2], A1.x, wg2); fma2(acc2[2][3], A1.y, wg2);
            fma2(acc2[3][0], A0.x, wo);  fma2(acc2[3][1], A0.y, wo);
            fma2(acc2[3][2], A1.x, wo);  fma2(acc2[3][3], A1.y, wo);
        }
    }
    #undef G_ISSUE
}

__device__ __forceinline__ void ksplit_merge(float* __restrict__ smemAll,
                                             u64t acc2[4][4], int half) {
    u64t* red = reinterpret_cast<u64t*>(smemAll);
    const int lt = threadIdx.x & 255;
    __syncthreads();
    if (half == 1) {
        #pragma unroll
        for (int g = 0; g < 4; g++)
            #pragma unroll
            for (int p = 0; p < 4; p++)
                red[lt*16 + g*4 + p] = acc2[g][p];
    }
    __syncthreads();
    if (half == 0) {
        #pragma unroll
        for (int g = 0; g < 4; g++)
            #pragma unroll
            for (int p = 0; p < 4; p++)
                add2(acc2[g][p], red[lt*16 + g*4 + p]);
    }
}

// Epilogue; pre2 optional second partial buffer.
__device__ __forceinline__ void lstm_epiT(u64t acc2[4][4],
                                          const float* __restrict__ pre,
                                          const float* __restrict__ pre2,
                                          const float* __restrict__ cinT,
                                          float* __restrict__ coutT,
                                          float* __restrict__ houtT, int ldh,
                                          float* __restrict__ houtN,
                                          int bm, int bn) {
    const int lt = threadIdx.x & 255;
    const int tx = lt & 31;
    const int ty = lt >> 5;
    const int n  = bn + tx;
    const int b0 = bm + ty*8;
    float cv[8], hv[8], co[8];
    *(float4*)&cv[0] = *(const float4*)&cinT[(size_t)n*BB + b0];
    *(float4*)&cv[4] = *(const float4*)&cinT[(size_t)n*BB + b0 + 4];
    #pragma unroll
    for (int p = 0; p < 4; p++) {
        float2 vi = unpack2(acc2[0][p]);
        float2 vf = unpack2(acc2[1][p]);
        float2 vg = unpack2(acc2[2][p]);
        float2 vo = unpack2(acc2[3][p]);
        #pragma unroll
        for (int sub = 0; sub < 2; sub++) {
            int idx = 2*p + sub;
            int b = b0 + idx;
            const float* pb = pre + (size_t)b*GG;
            float gi = pb[0*HH + n] + (sub ? vi.y : vi.x);
            float gf = pb[1*HH + n] + (sub ? vf.y : vf.x);
            float gg = pb[2*HH + n] + (sub ? vg.y : vg.x);
            float go = pb[3*HH + n] + (sub ? vo.y : vo.x);
            if (pre2) {
                const float* pc = pre2 + (size_t)b*GG;
                gi += pc[0*HH + n]; gf += pc[1*HH + n];
                gg += pc[2*HH + n]; go += pc[3*HH + n];
            }
            float cn = sigf(gf)*cv[idx] + sigf(gi)*tanhf_(gg);
            co[idx] = cn;
            hv[idx] = sigf(go)*tanhf_(cn);
        }
    }
    *(float4*)&coutT[(size_t)n*BB + b0]     = *(float4*)&co[0];
    *(float4*)&coutT[(size_t)n*BB + b0 + 4] = *(float4*)&co[4];
    *(float4*)&houtT[(size_t)n*ldh + b0]     = *(float4*)&hv[0];
    *(float4*)&houtT[(size_t)n*ldh + b0 + 4] = *(float4*)&hv[4];
    if (houtN) {
        #pragma unroll
        for (int i = 0; i < 8; i++) houtN[(size_t)(b0+i)*HH + n] = hv[i];
    }
}

__device__ __forceinline__ void part_store(u64t acc2[4][4],
                                           const float* __restrict__ bias,
                                           float* __restrict__ outp,
                                           int bm, int bn) {
    const int lt = threadIdx.x & 255;
    const int tx = lt & 31;
    const int ty = lt >> 5;
    const int n = bn + tx;
    #pragma unroll
    for (int g = 0; g < 4; g++) {
        float bv = bias[g*HH + n];
        #pragma unroll
        for (int p = 0; p < 4; p++) {
            float2 v = unpack2(acc2[g][p]);
            int b0 = bm + ty*8 + 2*p;
            outp[(size_t)(b0+0)*GG + g*HH + n] = v.x + bv;
            outp[(size_t)(b0+1)*GG + g*HH + n] = v.y + bv;
        }
    }
}

#define ZERO_ACC(a) { _Pragma("unroll") for (int g_=0; g_<4; g_++) { \
    _Pragma("unroll") for (int p_=0; p_<4; p_++) (a)[g_][p_] = 0ull; } }

// ---------------- encoder recurrent step ----------------
struct DirT {
    const float* pre;
    const float* hinT; int lda;
    const float* cinT;
    float* coutT;
    float* houtT;
    const float* WT4;
};

__global__ __launch_bounds__(512, 1) void lstm_stepT(DirT A0, DirT A1) {
    extern __shared__ __align__(16) float S[];
    DirT d = blockIdx.z ? A1 : A0;
    const int half = threadIdx.x >> 8;
    float* base = S + half*GHALF;
    int bm = blockIdx.y * 64;
    int bn = blockIdx.x * 32;
    u64t acc2[4][4];
    ZERO_ACC(acc2);
    gate_gemm_ca<16>(d.hinT, d.lda, d.WT4, bm, bn, half*256, base, acc2);
    ksplit_merge(S, acc2, half);
    if (half == 0)
        lstm_epiT(acc2, d.pre, nullptr, d.cinT, d.coutT, d.houtT, LDH, nullptr, bm, bn);
}

// ---------------- decoder phase Y: cell1 (z=0) || part0' (z=1) ----------------
__global__ __launch_bounds__(512, 1) void dec_Y(const float* __restrict__ dh0T,
                                                const float* __restrict__ w4ih1,
                                                const float* __restrict__ part1a,
                                                const float* __restrict__ part1b,
                                                float* __restrict__ dc1T,
                                                float* __restrict__ dh1T,
                                                float* __restrict__ dh1n,
                                                const float* __restrict__ w4hh0,
                                                const float* __restrict__ zerob,
                                                float* __restrict__ part0) {
    extern __shared__ __align__(16) float S[];
    const int half = threadIdx.x >> 8;
    float* base = S + half*GHALF;
    int bm = blockIdx.y * 64;
    int bn = blockIdx.x * 32;
    u64t acc2[4][4];
    ZERO_ACC(acc2);
    if (blockIdx.z == 0) {
        gate_gemm_ca<16>(dh0T, BB, w4ih1, bm, bn, half*256, base, acc2);
        ksplit_merge(S, acc2, half);
        if (half == 0) lstm_epiT(acc2, part1a, part1b, dc1T, dc1T, dh1T, BB, dh1n, bm, bn);
    } else {
        gate_gemm_ca<16>(dh0T, BB, w4hh0, bm, bn, half*256, base, acc2);
        ksplit_merge(S, acc2, half);
        if (half == 0) part_store(acc2, zerob, part0, bm, bn);
    }
}

// ---- phase Z: logits+argmax+cell0 (z=0) || part1a (z=1) || part1b (z=2) -----
__global__ __launch_bounds__(512, 1) void dec_Z(const float* __restrict__ dh1T,
                                                const float* __restrict__ dh1n,
                                                const float* __restrict__ Wout,
                                                const float* __restrict__ bout,
                                                const float* __restrict__ w4hh1,
                                                const float* __restrict__ b1,
                                                const float* __restrict__ zerob,
                                                float* __restrict__ part1a,
                                                float* __restrict__ part1b,
                                                const float* __restrict__ Ptab,
                                                const float* __restrict__ part0,
                                                float* __restrict__ dc0,
                                                float* __restrict__ dh0T,
                                                float* __restrict__ recon,
                                                int t) {
    extern __shared__ __align__(16) float S[];
    if (blockIdx.z >= 1) {
        const int half = threadIdx.x >> 8;
        float* base = S + half*GHALF;
        int bm = blockIdx.y * 64;
        int bn = blockIdx.x * 32;
        int kb = (blockIdx.z - 1) * 256 + half*128;
        u64t acc2[4][4];
        ZERO_ACC(acc2);
        gate_gemm_ca<8>(dh1T, BB, w4hh1, bm, bn, kb, base, acc2);
        ksplit_merge(S, acc2, half);
        if (half == 0) {
            if (blockIdx.z == 1) part_store(acc2, b1,    part1a, bm, bn);
            else                 part_store(acc2, zerob, part1b, bm, bn);
        }
        return;
    }
    const int tid = threadIdx.x;
    const int bid = blockIdx.y*16 + blockIdx.x;
    const int b0r = bid * 4;
    float* sh = S;
    float* sv = S + 4*HH;
    int*   si = (int*)(S + 4*HH + 4*VV);
    ((float4*)sh)[tid] = ((const float4*)(dh1n + (size_t)b0r*HH))[tid];
    __syncthreads();
    const int v = tid & 127;
    const int r = tid >> 7;
    const float4* w4 = (const float4*)(Wout + (size_t)v*HH);
    const float* shr = sh + r*HH;
    float acc = bout[v];
    #pragma unroll 8
    for (int k = 0; k < HH/4; k++) {
        float4 wv = w4[k];
        float4 s4 = *(const float4*)&shr[k*4];
        acc += s4.x*wv.x + s4.y*wv.y + s4.z*wv.z + s4.w*wv.w;
    }
    recon[(size_t)(b0r+r)*TT*VV + (size_t)t*VV + v] = acc;
    sv[r*VV + v] = acc;
    si[r*VV + v] = v;
    __syncthreads();
    for (int s2 = 64; s2 > 0; s2 >>= 1) {
        if (v < s2) {
            float ov = sv[r*VV + v + s2]; int oi = si[r*VV + v + s2];
            if (ov > sv[r*VV + v] || (ov == sv[r*VV + v] && oi < si[r*VV + v])) {
                sv[r*VV + v] = ov; si[r*VV + v] = oi;
            }
        }
        __syncthreads();
    }
    const int tk = si[r*VV];
    const int b = b0r + r;
    const int h0c = v * 4;
    const float* pt = Ptab + (size_t)tk*GG;
    const float* p0 = part0 + (size_t)b*GG;
    float4 pi = *(const float4*)&pt[0*HH + h0c]; float4 qi = *(const float4*)&p0[0*HH + h0c];
    float4 pf = *(const float4*)&pt[1*HH + h0c]; float4 qf = *(const float4*)&p0[1*HH + h0c];
    float4 pg = *(const float4*)&pt[2*HH + h0c]; float4 qg = *(const float4*)&p0[2*HH + h0c];
    float4 po = *(const float4*)&pt[3*HH + h0c]; float4 qo = *(const float4*)&p0[3*HH + h0c];
    float4 c4 = *(const float4*)&dc0[(size_t)b*HH + h0c];
    float gi[4] = {pi.x+qi.x, pi.y+qi.y, pi.z+qi.z, pi.w+qi.w};
    float gf[4] = {pf.x+qf.x, pf.y+qf.y, pf.z+qf.z, pf.w+qf.w};
    float gg[4] = {pg.x+qg.x, pg.y+qg.y, pg.z+qg.z, pg.w+qg.w};
    float go[4] = {po.x+qo.x, po.y+qo.y, po.z+qo.z, po.w+qo.w};
    float cc[4] = {c4.x, c4.y, c4.z, c4.w};
    float co[4];
    #pragma unroll
    for (int j = 0; j < 4; j++) {
        float cn = sigf(gf[j])*cc[j] + sigf(gi[j])*tanhf_(gg[j]);
        co[j] = cn;
        dh0T[(size_t)(h0c+j)*BB + b] = sigf(go[j])*tanhf_(cn);
    }
    *(float4*)&dc0[(size_t)b*HH + h0c] = make_float4(co[0], co[1], co[2], co[3]);
}

// ---------------- cell0 at t=0 ----------------
__global__ __launch_bounds__(128) void cell0_init_kernel(const float* __restrict__ Ptab,
                                                         const float* __restrict__ part0,
                                                         float* __restrict__ dc0,
                                                         float* __restrict__ dh0T) {
    const int b = blockIdx.x;
    const int h0c = threadIdx.x * 4;
    const float* pt = Ptab + (size_t)1*GG;
    const float* p0 = part0 + (size_t)b*GG;
    float4 pi = *(const float4*)&pt[0*HH + h0c]; float4 qi = *(const float4*)&p0[0*HH + h0c];
    float4 pf = *(const float4*)&pt[1*HH + h0c]; float4 qf = *(const float4*)&p0[1*HH + h0c];
    float4 pg = *(const float4*)&pt[2*HH + h0c]; float4 qg = *(const float4*)&p0[2*HH + h0c];
    float4 po = *(const float4*)&pt[3*HH + h0c]; float4 qo = *(const float4*)&p0[3*HH + h0c];
    float4 c4 = *(const float4*)&dc0[(size_t)b*HH + h0c];
    float gi[4] = {pi.x+qi.x, pi.y+qi.y, pi.z+qi.z, pi.w+qi.w};
    float gf[4] = {pf.x+qf.x, pf.y+qf.y, pf.z+qf.z, pf.w+qf.w};
    float gg[4] = {pg.x+qg.x, pg.y+qg.y, pg.z+qg.z, pg.w+qg.w};
    float go[4] = {po.x+qo.x, po.y+qo.y, po.z+qo.z, po.w+qo.w};
    float cc[4] = {c4.x, c4.y, c4.z, c4.w};
    float co[4];
    #pragma unroll
    for (int j = 0; j < 4; j++) {
        float cn = sigf(gf[j])*cc[j] + sigf(gi[j])*tanhf_(gg[j]);
        co[j] = cn;
        dh0T[(size_t)(h0c+j)*BB + b] = sigf(go[j])*tanhf_(cn);
    }
    *(float4*)&dc0[(size_t)b*HH + h0c] = make_float4(co[0], co[1], co[2], co[3]);
}

// ---------------- mu/logvar heads ----------------
__global__ __launch_bounds__(256) void head_kernel(const float* __restrict__ hfT,
                                                   const float* __restrict__ hbT,
                                                   const float* __restrict__ Wmu,
                                                   const float* __restrict__ bmu,
                                                   const float* __restrict__ Wlv,
                                                   const float* __restrict__ blv,
                                                   float* __restrict__ out_mu,
                                                   float* __restrict__ out_lv,
                                                   float* __restrict__ zbuf) {
    int b = blockIdx.x;
    int tid = threadIdx.x;
    __shared__ float sh[2*HH];
    for (int i = tid; i < HH; i += 256) {
        sh[i]      = hfT[(size_t)i*LDH + b];
        sh[HH + i] = hbT[(size_t)i*LDH + b];
    }
    __syncthreads();
    const float* W;
    float acc;
    int l;
    if (tid < LL) { l = tid;      W = Wmu + (size_t)l*2*HH; acc = bmu[l]; }
    else          { l = tid - LL; W = Wlv + (size_t)l*2*HH; acc = blv[l]; }
    #pragma unroll 8
    for (int k = 0; k < 2*HH; k++) acc += sh[k]*W[k];
    if (tid < LL) { out_mu[b*LL + l] = acc; zbuf[b*LL + l] = acc; }
    else          { out_lv[b*LL + l] = acc; }
}

// ---------------- decoder init ----------------
__global__ __launch_bounds__(512) void dec_init_kernel(const float* __restrict__ z,
                                                       const float* __restrict__ W,
                                                       const float* __restrict__ bias,
                                                       float* __restrict__ h0T,
                                                       float* __restrict__ h1T,
                                                       float* __restrict__ h1n,
                                                       float* __restrict__ c0n,
                                                       float* __restrict__ c1T) {
    int b = blockIdx.x;
    int tid = threadIdx.x;
    __shared__ float sz[LL];
    if (tid < LL) sz[tid] = z[b*LL + tid];
    __syncthreads();
    float acc = bias[tid];
    const float* w = W + (size_t)tid*LL;
    #pragma unroll 8
    for (int k = 0; k < LL; k++) acc += sz[k]*w[k];
    h0T[(size_t)tid*BB + b] = acc;
    h1T[(size_t)tid*BB + b] = acc;
    h1n[(size_t)b*HH + tid] = acc;
    c0n[(size_t)b*HH + tid] = 0.0f;
    c1T[(size_t)tid*BB + b] = 0.0f;
}

// =================================== host launcher ====================================
extern "C" void kernel_launch(void* const* d_in, const int* in_sizes, int n_in,
                              void* d_out, int out_size) {
    const int*   x           = (const int*)  d_in[0];
    const float* emb         = (const float*)d_in[1];
    const float* enc_wih_l0  = (const float*)d_in[2];
    const float* enc_whh_l0  = (const float*)d_in[3];
    const float* enc_b_l0    = (const float*)d_in[4];
    const float* enc_wih_l1  = (const float*)d_in[5];
    const float* enc_whh_l1  = (const float*)d_in[6];
    const float* enc_b_l1    = (const float*)d_in[7];
    const float* fc_mu_w     = (const float*)d_in[8];
    const float* fc_mu_b     = (const float*)d_in[9];
    const float* fc_lv_w     = (const float*)d_in[10];
    const float* fc_lv_b     = (const float*)d_in[11];
    const float* dec_in_w    = (const float*)d_in[12];
    const float* dec_in_b    = (const float*)d_in[13];
    const float* dec_wih     = (const float*)d_in[14];
    const float* dec_whh     = (const float*)d_in[15];
    const float* dec_b       = (const float*)d_in[16];
    const float* dec_out_w   = (const float*)d_in[17];
    const float* dec_out_b   = (const float*)d_in[18];

    float* out       = (float*)d_out;
    float* out_recon = out;
    float* out_mu    = out + (size_t)BB*TT*VV;
    float* out_lv    = out_mu + (size_t)BB*LL;

    float *seqT, *seq1T, *y1fT, *y1bT, *preF, *preB;
    float *c0fT, *c0bT, *c1fT, *c1bT, *zeros, *zbuf;
    float *dh0T, *dh1T, *dh1n, *dc0, *dc1T, *part0, *part1a, *part1b, *ptab, *embT, *wt, *wt4;
    cudaGetSymbolAddress((void**)&seqT,  g_seqT);
    cudaGetSymbolAddress((void**)&seq1T, g_seq1T);
    cudaGetSymbolAddress((void**)&y1fT,  g_y1fT);
    cudaGetSymbolAddress((void**)&y1bT,  g_y1bT);
    cudaGetSymbolAddress((void**)&preF,  g_preF);
    cudaGetSymbolAddress((void**)&preB,  g_preB);
    cudaGetSymbolAddress((void**)&c0fT,  g_c0fT);
    cudaGetSymbolAddress((void**)&c0bT,  g_c0bT);
    cudaGetSymbolAddress((void**)&c1fT,  g_c1fT);
    cudaGetSymbolAddress((void**)&c1bT,  g_c1bT);
    cudaGetSymbolAddress((void**)&zeros, g_zeros);
    cudaGetSymbolAddress((void**)&zbuf,  g_z);
    cudaGetSymbolAddress((void**)&dh0T,  g_dh0T);
    cudaGetSymbolAddress((void**)&dh1T,  g_dh1T);
    cudaGetSymbolAddress((void**)&dh1n,  g_dh1n);
    cudaGetSymbolAddress((void**)&dc0,   g_dc0);
    cudaGetSymbolAddress((void**)&dc1T,  g_dc1T);
    cudaGetSymbolAddress((void**)&part0, g_part0);
    cudaGetSymbolAddress((void**)&part1a,g_part1a);
    cudaGetSymbolAddress((void**)&part1b,g_part1b);
    cudaGetSymbolAddress((void**)&ptab,  g_ptab);
    cudaGetSymbolAddress((void**)&embT,  g_embT);
    cudaGetSymbolAddress((void**)&wt,    g_wt);
    cudaGetSymbolAddress((void**)&wt4,   g_wt4);

    const size_t M1 = 1024*1024;
    float* wtA0f = wt;
    float* wtA0b = wt + 1*M1;
    float* wtA1f = wt + 2*M1;
    float* wtA1b = wt + 4*M1;
    float* wtPt  = wt + 6*M1;
    float* wtD0  = wt + 7*M1;
    float* wtD1  = wt + 8*M1;
    float* w4e0f = wt4;
    float* w4e0b = wt4 + 1*M1;
    float* w4e1f = wt4 + 2*M1;
    float* w4e1b = wt4 + 3*M1;
    float* w4ih1 = wt4 + 4*M1;
    float* w4hh0 = wt4 + 5*M1;
    float* w4hh1 = wt4 + 6*M1;

    const float* dWih0 = dec_wih;
    const float* dWih1 = dec_wih + (size_t)GG*HH;
    const float* dWhh0 = dec_whh;
    const float* dWhh1 = dec_whh + (size_t)GG*HH;
    const float* db0   = dec_b;
    const float* db1   = dec_b + GG;

    // dynamic smem opt-in (idempotent host-side calls; legal during capture)
    const int GB = GSMEM * 4;   // 73728 bytes
    cudaFuncSetAttribute(lstm_stepT, cudaFuncAttributeMaxDynamicSharedMemorySize, GB);
    cudaFuncSetAttribute(dec_Y,      cudaFuncAttributeMaxDynamicSharedMemorySize, GB);
    cudaFuncSetAttribute(dec_Z,      cudaFuncAttributeMaxDynamicSharedMemorySize, GB);

    // ---- transforms ----
    embT_kernel<<<2048, 256>>>(x, emb, seqT);
    wt_kernel<<<512, 256>>>(emb, embT, VV, HH);
    wt_kernel<<<1024, 256>>>(enc_wih_l0,                 wtA0f, GG, HH);
    wt_kernel<<<1024, 256>>>(enc_wih_l0 + (size_t)GG*HH, wtA0b, GG, HH);
    wt_kernel<<<2048, 256>>>(enc_wih_l1,                    wtA1f, GG, 2*HH);
    wt_kernel<<<2048, 256>>>(enc_wih_l1 + (size_t)GG*2*HH,  wtA1b, GG, 2*HH);
    wt_kernel<<<1024, 256>>>(dWih0, wtPt, GG, HH);
    wt_kernel<<<1024, 256>>>(dWhh0, wtD0, GG, HH);
    wt_kernel<<<1024, 256>>>(dWhh1, wtD1, GG, HH);
    wt4_kernel<<<1024, 256>>>(enc_whh_l0,                 w4e0f);
    wt4_kernel<<<1024, 256>>>(enc_whh_l0 + (size_t)GG*HH, w4e0b);
    wt4_kernel<<<1024, 256>>>(enc_whh_l1,                 w4e1f);
    wt4_kernel<<<1024, 256>>>(enc_whh_l1 + (size_t)GG*HH, w4e1b);
    wt4_kernel<<<1024, 256>>>(dWih1, w4ih1);
    wt4_kernel<<<1024, 256>>>(dWhh0, w4hh0);
    wt4_kernel<<<1024, 256>>>(dWhh1, w4hh1);

    // ---- Ptab ----
    sgemm_ca<<<dim3(GG/128, VV/128), 256>>>(embT, wtPt, db0, ptab, VV, GG, HH);

    // ---- encoder layer 0 ----
    dim3 preGrd(GG/128, LDH/128);
    sgemm_ca<<<preGrd, 256>>>(seqT, wtA0f, enc_b_l0,      preF, LDH, GG, HH);
    sgemm_ca<<<preGrd, 256>>>(seqT, wtA0b, enc_b_l0 + GG, preB, LDH, GG, HH);

    dim3 stepGrd(HH/32, BB/64, 2);
    float* seq1Tb = seq1T + (size_t)HH*LDH;
    for (int s = 0; s < TT; s++) {
        int tf = s, tb = TT-1-s;
        DirT df = { preF + (size_t)tf*BB*GG,
                    s ? seq1T + (size_t)(tf-1)*BB : zeros, s ? LDH : BB,
                    s ? c0fT : zeros, c0fT,
                    seq1T + (size_t)tf*BB, w4e0f };
        DirT db = { preB + (size_t)tb*BB*GG,
                    s ? seq1Tb + (size_t)(tb+1)*BB : zeros, s ? LDH : BB,
                    s ? c0bT : zeros, c0bT,
                    seq1Tb + (size_t)tb*BB, w4e0b };
        lstm_stepT<<<stepGrd, 512, GB>>>(df, db);
    }

    // ---- encoder layer 1 ----
    sgemm_ca<<<preGrd, 256>>>(seq1T, wtA1f, enc_b_l1,      preF, LDH, GG, 2*HH);
    sgemm_ca<<<preGrd, 256>>>(seq1T, wtA1b, enc_b_l1 + GG, preB, LDH, GG, 2*HH);
    for (int s = 0; s < TT; s++) {
        int tf = s, tb = TT-1-s;
        DirT df = { preF + (size_t)tf*BB*GG,
                    s ? y1fT + (size_t)(tf-1)*BB : zeros, s ? LDH : BB,
                    s ? c1fT : zeros, c1fT,
                    y1fT + (size_t)tf*BB, w4e1f };
        DirT db = { preB + (size_t)tb*BB*GG,
                    s ? y1bT + (size_t)(tb+1)*BB : zeros, s ? LDH : BB,
                    s ? c1bT : zeros, c1bT,
                    y1bT + (size_t)tb*BB, w4e1b };
        lstm_stepT<<<stepGrd, 512, GB>>>(df, db);
    }

    // ---- heads ----
    head_kernel<<<BB, 256>>>(y1fT + (size_t)(TT-1)*BB, y1bT,
                             fc_mu_w, fc_mu_b, fc_lv_w, fc_lv_b,
                             out_mu, out_lv, zbuf);

    // ---- decoder init ----
    dec_init_kernel<<<BB, 512>>>(zbuf, dec_in_w, dec_in_b, dh0T, dh1T, dh1n, dc0, dc1T);
    dim3 partGrd(GG/128, BB/128);
    sgemm_ca<<<partGrd, 256>>>(dh0T, wtD0, zeros, part0,  BB, GG, HH);
    sgemm_ca<<<partGrd, 256>>>(dh1T, wtD1, db1,   part1a, BB, GG, HH);
    cudaMemsetAsync(part1b, 0, (size_t)BB*GG*sizeof(float));
    cell0_init_kernel<<<BB, 128>>>(ptab, part0, dc0, dh0T);

    // ---- autoregressive decode ----
    dim3 yGrd(HH/32, BB/64, 2);
    dim3 zGrd(HH/32, BB/64, 3);
    for (int t = 0; t < TT; t++) {
        dec_Y<<<yGrd, 512, GB>>>(dh0T, w4ih1, part1a, part1b, dc1T, dh1T, dh1n,
                                 w4hh0, zeros, part0);
        dec_Z<<<zGrd, 512, GB>>>(dh1T, dh1n, dec_out_w, dec_out_b, w4hh1, db1, zeros,
                                 part1a, part1b, ptab, part0, dc0, dh0T, out_recon, t);
    }
}

// round 14
// speedup vs baseline: 1.1685x; 1.1679x over previous
#include <cuda_runtime.h>
#include <cuda_fp16.h>
#include <cstdint>
#include <math.h>

#define TT 128
#define BB 256
#define HH 512
#define GG 2048
#define VV 128
#define LL 128
#define LDH (TT*BB)

typedef unsigned long long u64t;

__device__ __forceinline__ u64t pack2(float x, float y) {
    u64t r; asm("mov.b64 %0, {%1, %2};" : "=l"(r) : "f"(x), "f"(y)); return r;
}
__device__ __forceinline__ void fma2(u64t& d, u64t a, u64t b) {
    asm("fma.rn.f32x2 %0, %1, %2, %0;" : "+l"(d) : "l"(a), "l"(b));
}
__device__ __forceinline__ void add2(u64t& d, u64t a) {
    asm("add.rn.f32x2 %0, %0, %1;" : "+l"(d) : "l"(a));
}
__device__ __forceinline__ float2 unpack2(u64t v) {
    float2 r; asm("mov.b64 {%0, %1}, %2;" : "=f"(r.x), "=f"(r.y) : "l"(v)); return r;
}
__device__ __forceinline__ unsigned smem_u32(const void* p) {
    return (unsigned)__cvta_generic_to_shared(p);
}
#define CP16(dst, src) asm volatile("cp.async.ca.shared.global [%0], [%1], 16;" :: "r"(dst), "l"((const void*)(src)) : "memory")
#define CP_COMMIT      asm volatile("cp.async.commit_group;" ::: "memory")
#define CP_WAIT1       asm volatile("cp.async.wait_group 1;" ::: "memory")
#define CP_WAIT0       asm volatile("cp.async.wait_group 0;" ::: "memory")

__device__ __forceinline__ float ex2f(float x) { float r; asm("ex2.approx.ftz.f32 %0, %1;" : "=f"(r) : "f"(x)); return r; }
__device__ __forceinline__ float rcpf(float x) { float r; asm("rcp.approx.ftz.f32 %0, %1;" : "=f"(r) : "f"(x)); return r; }
__device__ __forceinline__ float sigf(float v)  { return rcpf(1.0f + ex2f(-1.4426950408889634f*v)); }
__device__ __forceinline__ float tanhf_(float v){ return 2.0f*rcpf(1.0f + ex2f(-2.8853900817779268f*v)) - 1.0f; }

// fp16 2-way split: v = h + l*2^-11, l stored pre-scaled by 2^11 (normal range)
__device__ __forceinline__ void split2h(float v, __half& h, __half& l) {
    h = __float2half(v);
    l = __float2half((v - __half2float(h)) * 2048.0f);
}

// ---------------- device scratch ----------------
__device__ __align__(16) float g_seq1T[2*HH*LDH];
__device__ __align__(16) float g_y1fT [HH*LDH];
__device__ __align__(16) float g_y1bT [HH*LDH];
__device__ __align__(16) float g_preF [TT*BB*GG];
__device__ __align__(16) float g_preB [TT*BB*GG];
__device__ __align__(16) float g_c0fT [HH*BB];
__device__ __align__(16) float g_c0bT [HH*BB];
__device__ __align__(16) float g_c1fT [HH*BB];
__device__ __align__(16) float g_c1bT [HH*BB];
__device__ __align__(16) float g_zeros[HH*BB];
__device__ __align__(16) float g_z    [BB*LL];
__device__ __align__(16) float g_dh0T [HH*BB];
__device__ __align__(16) float g_dh1T [HH*BB];
__device__ __align__(16) float g_dh1n [BB*HH];
__device__ __align__(16) float g_dc0  [BB*HH];
__device__ __align__(16) float g_dc1T [HH*BB];
__device__ __align__(16) float g_part0 [BB*GG];
__device__ __align__(16) float g_part1a[BB*GG];
__device__ __align__(16) float g_part1b[BB*GG];
__device__ __align__(16) float g_ptab [VV*GG];
__device__ __align__(16) float g_embT [HH*VV];
__device__ __align__(16) float g_wt   [3*1024*1024];
__device__ __align__(16) float g_wt4  [7*1024*1024];
// fp16 2-way splits for HMMA pre-GEMMs
__device__ __align__(16) __half g_a0h[LDH*HH],    g_a0l[LDH*HH];
__device__ __align__(16) __half g_a1h[LDH*2*HH],  g_a1l[LDH*2*HH];
__device__ __align__(16) __half g_w0h[2*GG*HH],   g_w0l[2*GG*HH];
__device__ __align__(16) __half g_w1h[2*GG*2*HH], g_w1l[2*GG*2*HH];

// ---------------- transforms ----------------
__global__ void wt_kernel(const float* __restrict__ in, float* __restrict__ out, int N, int K) {
    int total = N*K;
    for (int i = blockIdx.x*blockDim.x + threadIdx.x; i < total; i += gridDim.x*blockDim.x) {
        int n = i % N; int k = i / N;
        out[i] = in[(size_t)n*K + k];
    }
}
__global__ void wt4_kernel(const float* __restrict__ in, float* __restrict__ out) {
    int total = HH*GG;
    for (int i = blockIdx.x*blockDim.x + threadIdx.x; i < total; i += gridDim.x*blockDim.x) {
        int g = i & 3; int n = (i >> 2) & 511; int k = i >> 11;
        out[i] = in[((size_t)(g*HH + n))*HH + k];
    }
}
__global__ void wsplit2(const float* __restrict__ in, __half* __restrict__ oh,
                        __half* __restrict__ ol, int total) {
    for (int i = blockIdx.x*blockDim.x + threadIdx.x; i < total; i += gridDim.x*blockDim.x) {
        __half h, l; split2h(in[i], h, l);
        oh[i] = h; ol[i] = l;
    }
}
__global__ void embsplit2(const int* __restrict__ x, const float* __restrict__ emb,
                          __half* __restrict__ ah, __half* __restrict__ al) {
    int total = LDH*HH;
    for (int i = blockIdx.x*blockDim.x + threadIdx.x; i < total; i += gridDim.x*blockDim.x) {
        int m = i >> 9, k = i & 511;
        int t = m / BB, b = m % BB;
        __half h, l; split2h(emb[x[b*TT + t]*HH + k], h, l);
        ah[i] = h; al[i] = l;
    }
}

// ============ HMMA fp16 2-split GEMM: C[M,N] = A@W^T + bias ============
// A[m][K] row-major (h,l), W[n][K] row-major (h,l) = col-major B for mma.row.col.
// CTA 128x64, 8 warps (4 m x 2 n), warp 32x32 (2 mt x 4 nt). K=32/stage, 2 buffers.
#define HM_STAGE 30720u   // Ah 10240 + Al 10240 + Wh 5120 + Wl 5120 (rows padded to 80B)
#define MMA16816(c, a0,a1,a2,a3, b0,b1) \
  asm volatile("mma.sync.aligned.m16n8k16.row.col.f32.f16.f16.f32 " \
    "{%0,%1,%2,%3}, {%4,%5,%6,%7}, {%8,%9}, {%0,%1,%2,%3};" \
    : "+f"((c)[0]), "+f"((c)[1]), "+f"((c)[2]), "+f"((c)[3]) \
    : "r"(a0),"r"(a1),"r"(a2),"r"(a3),"r"(b0),"r"(b1))

__global__ __launch_bounds__(256, 2) void mma_hm(
    const __half* __restrict__ Ah, const __half* __restrict__ Al,
    const __half* __restrict__ Wh, const __half* __restrict__ Wl,
    const float* __restrict__ bias, float* __restrict__ C, int N, int K) {
    extern __shared__ __align__(16) char HSm[];
    unsigned sb = smem_u32(HSm);
    const int tid = threadIdx.x;
    const int lane = tid & 31;
    const int wid = tid >> 5;
    const int wmB = (wid & 3) * 32;
    const int wnB = (wid >> 2) * 32;
    const int bm = blockIdx.y * 128;
    const int bn = blockIdx.x * 64;
    const int NS = K / 32;

    const __half* Asrc[2] = { Ah + (size_t)bm*K, Al + (size_t)bm*K };
    const __half* Wsrc[2] = { Wh + (size_t)bn*K, Wl + (size_t)bn*K };

    #define HLOAD(s) { unsigned db_ = sb + (unsigned)((s)&1)*HM_STAGE; size_t kb_ = (size_t)(s)*32; \
        _Pragma("unroll") for (int j = 0; j < 4; j++) { \
            int c_ = tid + j*256; int mt_ = c_ >> 9; int rk_ = c_ & 511; \
            int r_ = rk_ >> 2; int o_ = (rk_ & 3) * 8; \
            CP16(db_ + (unsigned)(mt_*10240 + r_*80 + o_*2), Asrc[mt_] + (size_t)r_*K + kb_ + o_); } \
        _Pragma("unroll") for (int j = 0; j < 2; j++) { \
            int c_ = tid + j*256; int mt_ = c_ >> 8; int rk_ = c_ & 255; \
            int r_ = rk_ >> 2; int o_ = (rk_ & 3) * 8; \
            CP16(db_ + (unsigned)(20480 + mt_*5120 + r_*80 + o_*2), Wsrc[mt_] + (size_t)r_*K + kb_ + o_); } \
        CP_COMMIT; }

    float c0[2][4][4], c1[2][4][4];
    #pragma unroll
    for (int mt = 0; mt < 2; mt++)
        #pragma unroll
        for (int nt = 0; nt < 4; nt++)
            #pragma unroll
            for (int q = 0; q < 4; q++) { c0[mt][nt][q] = 0.0f; c1[mt][nt][q] = 0.0f; }

    HLOAD(0); HLOAD(1);
    CP_WAIT1; __syncthreads();

    const int arow = lane >> 2;          // 0..7
    const int acol = (lane & 3) * 2;     // 0,2,4,6

    for (int s = 0; s < NS; s++) {
        const char* bufb = HSm + (s & 1)*HM_STAGE;
        #pragma unroll
        for (int kk = 0; kk < 32; kk += 16) {
            uint32_t BH[4][2], BL[4][2];
            #pragma unroll
            for (int nt = 0; nt < 4; nt++) {
                const char* wb = bufb + 20480 + (wnB + nt*8 + arow)*80 + (acol + kk)*2;
                BH[nt][0] = *(const uint32_t*)wb;
                BH[nt][1] = *(const uint32_t*)(wb + 16);
                BL[nt][0] = *(const uint32_t*)(wb + 5120);
                BL[nt][1] = *(const uint32_t*)(wb + 5120 + 16);
            }
            #pragma unroll
            for (int mt = 0; mt < 2; mt++) {
                const char* ab = bufb + (wmB + mt*16 + arow)*80 + (acol + kk)*2;
                uint32_t AH0 = *(const uint32_t*)ab;
                uint32_t AH1 = *(const uint32_t*)(ab + 640);
                uint32_t AH2 = *(const uint32_t*)(ab + 16);
                uint32_t AH3 = *(const uint32_t*)(ab + 640 + 16);
                uint32_t AL0 = *(const uint32_t*)(ab + 10240);
                uint32_t AL1 = *(const uint32_t*)(ab + 10240 + 640);
                uint32_t AL2 = *(const uint32_t*)(ab + 10240 + 16);
                uint32_t AL3 = *(const uint32_t*)(ab + 10240 + 640 + 16);
                #pragma unroll
                for (int nt = 0; nt < 4; nt++) {
                    MMA16816(c0[mt][nt], AH0,AH1,AH2,AH3, BH[nt][0],BH[nt][1]);
                    MMA16816(c1[mt][nt], AH0,AH1,AH2,AH3, BL[nt][0],BL[nt][1]);
                    MMA16816(c1[mt][nt], AL0,AL1,AL2,AL3, BH[nt][0],BH[nt][1]);
                }
            }
        }
        if (s == NS - 1) break;
        __syncthreads();
        if (s + 2 < NS) { HLOAD(s+2); CP_WAIT1; }
        else            { CP_WAIT0; }
        __syncthreads();
    }

    const float INV = 4.8828125e-4f;   // 2^-11
    #pragma unroll
    for (int mt = 0; mt < 2; mt++) {
        #pragma unroll
        for (int nt = 0; nt < 4; nt++) {
            int m0 = bm + wmB + mt*16 + arow;
            int n0 = bn + wnB + nt*8 + acol;
            float b0v = bias[n0], b1v = bias[n0+1];
            float2 o0 = make_float2(c0[mt][nt][0] + c1[mt][nt][0]*INV + b0v,
                                    c0[mt][nt][1] + c1[mt][nt][1]*INV + b1v);
            float2 o1 = make_float2(c0[mt][nt][2] + c1[mt][nt][2]*INV + b0v,
                                    c0[mt][nt][3] + c1[mt][nt][3]*INV + b1v);
            *(float2*)&C[(size_t)m0*N + n0]     = o0;
            *(float2*)&C[(size_t)(m0+8)*N + n0] = o1;
        }
    }
    #undef HLOAD
}

// ================= sgemm_ca (round-9 2-buffer) for small GEMMs =================
__global__ __launch_bounds__(256, 2) void sgemm_ca(const float* __restrict__ AT,
                                                   const float* __restrict__ WT,
                                                   const float* __restrict__ bias,
                                                   float* __restrict__ C,
                                                   int M, int N, int K) {
    __shared__ __align__(16) float S[2*4096];
    const int bm = blockIdx.y * 128;
    const int bn = blockIdx.x * 128;
    const int tid = threadIdx.x;
    const int tx = tid % 16;
    const int ty = tid / 16;
    const int NS = K / 16;
    const int ck  = tid >> 5;
    const int co  = (tid & 31) * 4;
    const float* asrc = AT + (size_t)ck*M + bm + co;
    const float* wsrc = WT + (size_t)ck*N + bn + co;
    unsigned sb = smem_u32(S);
    unsigned adst = sb + ((ck*128 + co) << 2);
    unsigned wdst = sb + ((2048 + ck*128 + co) << 2);

    #define PRE_ISSUE(s) { unsigned o_ = ((s)&1)*16384u; size_t ka_ = (size_t)(s)*16*M, kw_ = (size_t)(s)*16*N; \
        CP16(adst + o_, asrc + ka_); CP16(adst + o_ + 4096u, asrc + ka_ + 8*(size_t)M); \
        CP16(wdst + o_, wsrc + kw_); CP16(wdst + o_ + 4096u, wsrc + kw_ + 8*(size_t)N); CP_COMMIT; }

    u64t acc2[4][8];
    #pragma unroll
    for (int p = 0; p < 4; p++)
        #pragma unroll
        for (int j = 0; j < 8; j++) acc2[p][j] = 0ull;

    PRE_ISSUE(0); PRE_ISSUE(1);
    CP_WAIT1; __syncthreads();

    for (int s = 0; s < NS; s++) {
        const float* Bq = S + (s & 1)*4096;
        #pragma unroll
        for (int k = 0; k < 16; k++) {
            ulonglong2 A0 = *(const ulonglong2*)&Bq[k*128 + ty*8];
            ulonglong2 A1 = *(const ulonglong2*)&Bq[k*128 + ty*8 + 4];
            u64t apair[4] = {A0.x, A0.y, A1.x, A1.y};
            float w[8];
            *(float4*)&w[0] = *(const float4*)&Bq[2048 + k*128 + tx*8];
            *(float4*)&w[4] = *(const float4*)&Bq[2048 + k*128 + tx*8 + 4];
            #pragma unroll
            for (int j = 0; j < 8; j++) {
                u64t w2 = pack2(w[j], w[j]);
                #pragma unroll
                for (int p = 0; p < 4; p++) fma2(acc2[p][j], apair[p], w2);
            }
        }
        if (s == NS - 1) break;
        __syncthreads();
        if (s + 2 < NS) { PRE_ISSUE(s+2); CP_WAIT1; }
        else            { CP_WAIT0; }
        __syncthreads();
    }

    float bb[8];
    *(float4*)&bb[0] = *(const float4*)(bias + bn + tx*8);
    *(float4*)&bb[4] = *(const float4*)(bias + bn + tx*8 + 4);
    #pragma unroll
    for (int p = 0; p < 4; p++) {
        float2 v[8];
        #pragma unroll
        for (int j = 0; j < 8; j++) v[j] = unpack2(acc2[p][j]);
        #pragma unroll
        for (int sub = 0; sub < 2; sub++) {
            size_t row = (size_t)(bm + ty*8 + 2*p + sub)*N + bn + tx*8;
            float o[8];
            #pragma unroll
            for (int j = 0; j < 8; j++) o[j] = (sub ? v[j].y : v[j].x) + bb[j];
            *(float4*)&C[row]     = *(float4*)&o[0];
            *(float4*)&C[row + 4] = *(float4*)&o[4];
        }
    }
    #undef PRE_ISSUE
}

// ====== gate GEMM core (round-9: 2-buffer, split-K, 512 thr, static smem) ======
#define GBUF 3072
#define GHALF (2*GBUF)
#define GSMEM (2*GHALF)

template<int NST>
__device__ __forceinline__ void gate_gemm_ca(const float* __restrict__ hT, int lda,
                                             const float* __restrict__ WT4,
                                             int bm, int bn, int kbeg,
                                             float* __restrict__ base,
                                             u64t acc2[4][4]) {
    const int lt = threadIdx.x & 255;
    const int tx = lt & 31;
    const int ty = lt >> 5;
    const float* hsrc = hT + (size_t)(kbeg + (lt >> 4))*lda + bm + (lt & 15)*4;
    const float* wsrc = WT4 + (size_t)(kbeg + (lt >> 5))*GG + (size_t)bn*4 + (lt & 31)*4;
    unsigned sb = smem_u32(base);
    unsigned hdst = sb + (((lt >> 4)*64 + (lt & 15)*4) << 2);
    unsigned wdst = sb + ((1024 + (lt >> 5)*128 + (lt & 31)*4) << 2);

    #define G_ISSUE(s) { unsigned o_ = ((s)&1)*(GBUF*4u); size_t kh_ = (size_t)(s)*16*lda, kw_ = (size_t)(s)*16*GG; \
        CP16(hdst + o_, hsrc + kh_); \
        CP16(wdst + o_, wsrc + kw_); CP16(wdst + o_ + 4096u, wsrc + kw_ + 8*(size_t)GG); CP_COMMIT; }

    G_ISSUE(0); G_ISSUE(1);
    CP_WAIT1; __syncthreads();

    #pragma unroll 2
    for (int s = 0; s < NST; s++) {
        const float* Bq = base + (s & 1)*GBUF;
        #pragma unroll
        for (int k = 0; k < 16; k++) {
            ulonglong2 A0 = *(const ulonglong2*)&Bq[k*64 + ty*8];
            ulonglong2 A1 = *(const ulonglong2*)&Bq[k*64 + ty*8 + 4];
            float4 wv = *(const float4*)&Bq[1024 + k*128 + tx*4];
            u64t wi  = pack2(wv.x, wv.x);
            u64t wf  = pack2(wv.y, wv.y);
            u64t wg2 = pack2(wv.z, wv.z);
            u64t wo  = pack2(wv.w, wv.w);
            fma2(acc2[0][0], A0.x, wi);  fma2(acc2[0][1], A0.y, wi);
            fma2(acc2[0][2], A1.x, wi);  fma2(acc2[0][3], A1.y, wi);
            fma2(acc2[1][0], A0.x, wf);  fma2(acc2[1][1], A0.y, wf);
            fma2(acc2[1][2], A1.x, wf);  fma2(acc2[1][3], A1.y, wf);
            fma2(acc2[2][0], A0.x, wg2); fma2(acc2[2][1], A0.y, wg2);
            fma2(acc2[2][2], A1.x, wg2); fma2(acc2[2][3], A1.y, wg2);
            fma2(acc2[3][0], A0.x, wo);  fma2(acc2[3][1], A0.y, wo);
            fma2(acc2[3][2], A1.x, wo);  fma2(acc2[3][3], A1.y, wo);
        }
        if (s == NST - 1) break;
        __syncthreads();
        if (s + 2 < NST) { G_ISSUE(s+2); CP_WAIT1; }
        else             { CP_WAIT0; }
        __syncthreads();
    }
    #undef G_ISSUE
}

__device__ __forceinline__ void ksplit_merge(float* __restrict__ smemAll,
                                             u64t acc2[4][4], int half) {
    u64t* red = reinterpret_cast<u64t*>(smemAll);
    const int lt = threadIdx.x & 255;
    __syncthreads();
    if (half == 1) {
        #pragma unroll
        for (int g = 0; g < 4; g++)
            #pragma unroll
            for (int p = 0; p < 4; p++)
                red[lt*16 + g*4 + p] = acc2[g][p];
    }
    __syncthreads();
    if (half == 0) {
        #pragma unroll
        for (int g = 0; g < 4; g++)
            #pragma unroll
            for (int p = 0; p < 4; p++)
                add2(acc2[g][p], red[lt*16 + g*4 + p]);
    }
}

// Epilogue: optional pre2; optional fp16 split A-feed (row stride 1024).
__device__ __forceinline__ void lstm_epiT(u64t acc2[4][4],
                                          const float* __restrict__ pre,
                                          const float* __restrict__ pre2,
                                          const float* __restrict__ cinT,
                                          float* __restrict__ coutT,
                                          float* __restrict__ houtT, int ldh,
                                          float* __restrict__ houtN,
                                          __half* __restrict__ abh,
                                          __half* __restrict__ abl,
                                          int bm, int bn) {
    const int lt = threadIdx.x & 255;
    const int tx = lt & 31;
    const int ty = lt >> 5;
    const int n  = bn + tx;
    const int b0 = bm + ty*8;
    float cv[8], hv[8], co[8];
    *(float4*)&cv[0] = *(const float4*)&cinT[(size_t)n*BB + b0];
    *(float4*)&cv[4] = *(const float4*)&cinT[(size_t)n*BB + b0 + 4];
    #pragma unroll
    for (int p = 0; p < 4; p++) {
        float2 vi = unpack2(acc2[0][p]);
        float2 vf = unpack2(acc2[1][p]);
        float2 vg = unpack2(acc2[2][p]);
        float2 vo = unpack2(acc2[3][p]);
        #pragma unroll
        for (int sub = 0; sub < 2; sub++) {
            int idx = 2*p + sub;
            int b = b0 + idx;
            const float* pb = pre + (size_t)b*GG;
            float gi = pb[0*HH + n] + (sub ? vi.y : vi.x);
            float gf = pb[1*HH + n] + (sub ? vf.y : vf.x);
            float gg = pb[2*HH + n] + (sub ? vg.y : vg.x);
            float go = pb[3*HH + n] + (sub ? vo.y : vo.x);
            if (pre2) {
                const float* pc = pre2 + (size_t)b*GG;
                gi += pc[0*HH + n]; gf += pc[1*HH + n];
                gg += pc[2*HH + n]; go += pc[3*HH + n];
            }
            float cn = sigf(gf)*cv[idx] + sigf(gi)*tanhf_(gg);
            co[idx] = cn;
            hv[idx] = sigf(go)*tanhf_(cn);
        }
    }
    *(float4*)&coutT[(size_t)n*BB + b0]     = *(float4*)&co[0];
    *(float4*)&coutT[(size_t)n*BB + b0 + 4] = *(float4*)&co[4];
    *(float4*)&houtT[(size_t)n*ldh + b0]     = *(float4*)&hv[0];
    *(float4*)&houtT[(size_t)n*ldh + b0 + 4] = *(float4*)&hv[4];
    if (houtN) {
        #pragma unroll
        for (int i = 0; i < 8; i++) houtN[(size_t)(b0+i)*HH + n] = hv[i];
    }
    if (abh) {
        #pragma unroll
        for (int i = 0; i < 8; i++) {
            __half h, l; split2h(hv[i], h, l);
            size_t idx = (size_t)(b0+i)*1024 + n;
            abh[idx] = h; abl[idx] = l;
        }
    }
}

__device__ __forceinline__ void part_store(u64t acc2[4][4],
                                           const float* __restrict__ bias,
                                           float* __restrict__ outp,
                                           int bm, int bn) {
    const int lt = threadIdx.x & 255;
    const int tx = lt & 31;
    const int ty = lt >> 5;
    const int n = bn + tx;
    #pragma unroll
    for (int g = 0; g < 4; g++) {
        float bv = bias[g*HH + n];
        #pragma unroll
        for (int p = 0; p < 4; p++) {
            float2 v = unpack2(acc2[g][p]);
            int b0 = bm + ty*8 + 2*p;
            outp[(size_t)(b0+0)*GG + g*HH + n] = v.x + bv;
            outp[(size_t)(b0+1)*GG + g*HH + n] = v.y + bv;
        }
    }
}

#define ZERO_ACC(a) { _Pragma("unroll") for (int g_=0; g_<4; g_++) { \
    _Pragma("unroll") for (int p_=0; p_<4; p_++) (a)[g_][p_] = 0ull; } }

struct DirT {
    const float* pre;
    const float* hinT; int lda;
    const float* cinT;
    float* coutT;
    float* houtT;
    const float* WT4;
    __half *abh, *abl;
};

__global__ __launch_bounds__(512, 1) void lstm_stepT(DirT A0, DirT A1) {
    __shared__ __align__(16) float S[GSMEM];
    DirT d = blockIdx.z ? A1 : A0;
    const int half = threadIdx.x >> 8;
    float* base = S + half*GHALF;
    int bm = blockIdx.y * 64;
    int bn = blockIdx.x * 32;
    u64t acc2[4][4];
    ZERO_ACC(acc2);
    gate_gemm_ca<16>(d.hinT, d.lda, d.WT4, bm, bn, half*256, base, acc2);
    ksplit_merge(S, acc2, half);
    if (half == 0)
        lstm_epiT(acc2, d.pre, nullptr, d.cinT, d.coutT, d.houtT, LDH, nullptr,
                  d.abh, d.abl, bm, bn);
}

__global__ __launch_bounds__(512, 1) void dec_Y(const float* __restrict__ dh0T,
                                                const float* __restrict__ w4ih1,
                                                const float* __restrict__ part1a,
                                                const float* __restrict__ part1b,
                                                float* __restrict__ dc1T,
                                                float* __restrict__ dh1T,
                                                float* __restrict__ dh1n,
                                                const float* __restrict__ w4hh0,
                                                const float* __restrict__ zerob,
                                                float* __restrict__ part0) {
    __shared__ __align__(16) float S[GSMEM];
    const int half = threadIdx.x >> 8;
    float* base = S + half*GHALF;
    int bm = blockIdx.y * 64;
    int bn = blockIdx.x * 32;
    u64t acc2[4][4];
    ZERO_ACC(acc2);
    if (blockIdx.z == 0) {
        gate_gemm_ca<16>(dh0T, BB, w4ih1, bm, bn, half*256, base, acc2);
        ksplit_merge(S, acc2, half);
        if (half == 0) lstm_epiT(acc2, part1a, part1b, dc1T, dc1T, dh1T, BB, dh1n,
                                 nullptr, nullptr, bm, bn);
    } else {
        gate_gemm_ca<16>(dh0T, BB, w4hh0, bm, bn, half*256, base, acc2);
        ksplit_merge(S, acc2, half);
        if (half == 0) part_store(acc2, zerob, part0, bm, bn);
    }
}

__global__ __launch_bounds__(512, 1) void dec_Z(const float* __restrict__ dh1T,
                                                const float* __restrict__ dh1n,
                                                const float* __restrict__ Wout,
                                                const float* __restrict__ bout,
                                                const float* __restrict__ w4hh1,
                                                const float* __restrict__ b1,
                                                const float* __restrict__ zerob,
                                                float* __restrict__ part1a,
                                                float* __restrict__ part1b,
                                                const float* __restrict__ Ptab,
                                                const float* __restrict__ part0,
                                                float* __restrict__ dc0,
                                                float* __restrict__ dh0T,
                                                float* __restrict__ recon,
                                                int t) {
    __shared__ __align__(16) float S[GSMEM];
    if (blockIdx.z >= 1) {
        const int half = threadIdx.x >> 8;
        float* base = S + half*GHALF;
        int bm = blockIdx.y * 64;
        int bn = blockIdx.x * 32;
        int kb = (blockIdx.z - 1) * 256 + half*128;
        u64t acc2[4][4];
        ZERO_ACC(acc2);
        gate_gemm_ca<8>(dh1T, BB, w4hh1, bm, bn, kb, base, acc2);
        ksplit_merge(S, acc2, half);
        if (half == 0) {
            if (blockIdx.z == 1) part_store(acc2, b1,    part1a, bm, bn);
            else                 part_store(acc2, zerob, part1b, bm, bn);
        }
        return;
    }
    const int tid = threadIdx.x;
    const int bid = blockIdx.y*16 + blockIdx.x;
    const int b0r = bid * 4;
    float* sh = S;
    float* sv = S + 4*HH;
    int*   si = (int*)(S + 4*HH + 4*VV);
    ((float4*)sh)[tid] = ((const float4*)(dh1n + (size_t)b0r*HH))[tid];
    __syncthreads();
    const int v = tid & 127;
    const int r = tid >> 7;
    const float4* w4 = (const float4*)(Wout + (size_t)v*HH);
    const float* shr = sh + r*HH;
    float acc = bout[v];
    #pragma unroll 8
    for (int k = 0; k < HH/4; k++) {
        float4 wv = w4[k];
        float4 s4 = *(const float4*)&shr[k*4];
        acc += s4.x*wv.x + s4.y*wv.y + s4.z*wv.z + s4.w*wv.w;
    }
    recon[(size_t)(b0r+r)*TT*VV + (size_t)t*VV + v] = acc;
    sv[r*VV + v] = acc;
    si[r*VV + v] = v;
    __syncthreads();
    for (int s2 = 64; s2 > 0; s2 >>= 1) {
        if (v < s2) {
            float ov = sv[r*VV + v + s2]; int oi = si[r*VV + v + s2];
            if (ov > sv[r*VV + v] || (ov == sv[r*VV + v] && oi < si[r*VV + v])) {
                sv[r*VV + v] = ov; si[r*VV + v] = oi;
            }
        }
        __syncthreads();
    }
    const int tk = si[r*VV];
    const int b = b0r + r;
    const int h0c = v * 4;
    const float* pt = Ptab + (size_t)tk*GG;
    const float* p0 = part0 + (size_t)b*GG;
    float4 pi = *(const float4*)&pt[0*HH + h0c]; float4 qi = *(const float4*)&p0[0*HH + h0c];
    float4 pf = *(const float4*)&pt[1*HH + h0c]; float4 qf = *(const float4*)&p0[1*HH + h0c];
    float4 pg = *(const float4*)&pt[2*HH + h0c]; float4 qg = *(const float4*)&p0[2*HH + h0c];
    float4 po = *(const float4*)&pt[3*HH + h0c]; float4 qo = *(const float4*)&p0[3*HH + h0c];
    float4 c4 = *(const float4*)&dc0[(size_t)b*HH + h0c];
    float gi[4] = {pi.x+qi.x, pi.y+qi.y, pi.z+qi.z, pi.w+qi.w};
    float gf[4] = {pf.x+qf.x, pf.y+qf.y, pf.z+qf.z, pf.w+qf.w};
    float gg[4] = {pg.x+qg.x, pg.y+qg.y, pg.z+qg.z, pg.w+qg.w};
    float go[4] = {po.x+qo.x, po.y+qo.y, po.z+qo.z, po.w+qo.w};
    float cc[4] = {c4.x, c4.y, c4.z, c4.w};
    float co[4];
    #pragma unroll
    for (int j = 0; j < 4; j++) {
        float cn = sigf(gf[j])*cc[j] + sigf(gi[j])*tanhf_(gg[j]);
        co[j] = cn;
        dh0T[(size_t)(h0c+j)*BB + b] = sigf(go[j])*tanhf_(cn);
    }
    *(float4*)&dc0[(size_t)b*HH + h0c] = make_float4(co[0], co[1], co[2], co[3]);
}

__global__ __launch_bounds__(128) void cell0_init_kernel(const float* __restrict__ Ptab,
                                                         const float* __restrict__ part0,
                                                         float* __restrict__ dc0,
                                                         float* __restrict__ dh0T) {
    const int b = blockIdx.x;
    const int h0c = threadIdx.x * 4;
    const float* pt = Ptab + (size_t)1*GG;
    const float* p0 = part0 + (size_t)b*GG;
    float4 pi = *(const float4*)&pt[0*HH + h0c]; float4 qi = *(const float4*)&p0[0*HH + h0c];
    float4 pf = *(const float4*)&pt[1*HH + h0c]; float4 qf = *(const float4*)&p0[1*HH + h0c];
    float4 pg = *(const float4*)&pt[2*HH + h0c]; float4 qg = *(const float4*)&p0[2*HH + h0c];
    float4 po = *(const float4*)&pt[3*HH + h0c]; float4 qo = *(const float4*)&p0[3*HH + h0c];
    float4 c4 = *(const float4*)&dc0[(size_t)b*HH + h0c];
    float gi[4] = {pi.x+qi.x, pi.y+qi.y, pi.z+qi.z, pi.w+qi.w};
    float gf[4] = {pf.x+qf.x, pf.y+qf.y, pf.z+qf.z, pf.w+qf.w};
    float gg[4] = {pg.x+qg.x, pg.y+qg.y, pg.z+qg.z, pg.w+qg.w};
    float go[4] = {po.x+qo.x, po.y+qo.y, po.z+qo.z, po.w+qo.w};
    float cc[4] = {c4.x, c4.y, c4.z, c4.w};
    float co[4];
    #pragma unroll
    for (int j = 0; j < 4; j++) {
        float cn = sigf(gf[j])*cc[j] + sigf(gi[j])*tanhf_(gg[j]);
        co[j] = cn;
        dh0T[(size_t)(h0c+j)*BB + b] = sigf(go[j])*tanhf_(cn);
    }
    *(float4*)&dc0[(size_t)b*HH + h0c] = make_float4(co[0], co[1], co[2], co[3]);
}

__global__ __launch_bounds__(256) void head_kernel(const float* __restrict__ hfT,
                                                   const float* __restrict__ hbT,
                                                   const float* __restrict__ Wmu,
                                                   const float* __restrict__ bmu,
                                                   const float* __restrict__ Wlv,
                                                   const float* __restrict__ blv,
                                                   float* __restrict__ out_mu,
                                                   float* __restrict__ out_lv,
                                                   float* __restrict__ zbuf) {
    int b = blockIdx.x;
    int tid = threadIdx.x;
    __shared__ float sh[2*HH];
    for (int i = tid; i < HH; i += 256) {
        sh[i]      = hfT[(size_t)i*LDH + b];
        sh[HH + i] = hbT[(size_t)i*LDH + b];
    }
    __syncthreads();
    const float* W;
    float acc;
    int l;
    if (tid < LL) { l = tid;      W = Wmu + (size_t)l*2*HH; acc = bmu[l]; }
    else          { l = tid - LL; W = Wlv + (size_t)l*2*HH; acc = blv[l]; }
    #pragma unroll 8
    for (int k = 0; k < 2*HH; k++) acc += sh[k]*W[k];
    if (tid < LL) { out_mu[b*LL + l] = acc; zbuf[b*LL + l] = acc; }
    else          { out_lv[b*LL + l] = acc; }
}

__global__ __launch_bounds__(512) void dec_init_kernel(const float* __restrict__ z,
                                                       const float* __restrict__ W,
                                                       const float* __restrict__ bias,
                                                       float* __restrict__ h0T,
                                                       float* __restrict__ h1T,
                                                       float* __restrict__ h1n,
                                                       float* __restrict__ c0n,
                                                       float* __restrict__ c1T) {
    int b = blockIdx.x;
    int tid = threadIdx.x;
    __shared__ float sz[LL];
    if (tid < LL) sz[tid] = z[b*LL + tid];
    __syncthreads();
    float acc = bias[tid];
    const float* w = W + (size_t)tid*LL;
    #pragma unroll 8
    for (int k = 0; k < LL; k++) acc += sz[k]*w[k];
    h0T[(size_t)tid*BB + b] = acc;
    h1T[(size_t)tid*BB + b] = acc;
    h1n[(size_t)b*HH + tid] = acc;
    c0n[(size_t)b*HH + tid] = 0.0f;
    c1T[(size_t)tid*BB + b] = 0.0f;
}

// =================================== host launcher ====================================
extern "C" void kernel_launch(void* const* d_in, const int* in_sizes, int n_in,
                              void* d_out, int out_size) {
    const int*   x           = (const int*)  d_in[0];
    const float* emb         = (const float*)d_in[1];
    const float* enc_wih_l0  = (const float*)d_in[2];
    const float* enc_whh_l0  = (const float*)d_in[3];
    const float* enc_b_l0    = (const float*)d_in[4];
    const float* enc_wih_l1  = (const float*)d_in[5];
    const float* enc_whh_l1  = (const float*)d_in[6];
    const float* enc_b_l1    = (const float*)d_in[7];
    const float* fc_mu_w     = (const float*)d_in[8];
    const float* fc_mu_b     = (const float*)d_in[9];
    const float* fc_lv_w     = (const float*)d_in[10];
    const float* fc_lv_b     = (const float*)d_in[11];
    const float* dec_in_w    = (const float*)d_in[12];
    const float* dec_in_b    = (const float*)d_in[13];
    const float* dec_wih     = (const float*)d_in[14];
    const float* dec_whh     = (const float*)d_in[15];
    const float* dec_b       = (const float*)d_in[16];
    const float* dec_out_w   = (const float*)d_in[17];
    const float* dec_out_b   = (const float*)d_in[18];

    float* out       = (float*)d_out;
    float* out_recon = out;
    float* out_mu    = out + (size_t)BB*TT*VV;
    float* out_lv    = out_mu + (size_t)BB*LL;

    float *seq1T, *y1fT, *y1bT, *preF, *preB;
    float *c0fT, *c0bT, *c1fT, *c1bT, *zeros, *zbuf;
    float *dh0T, *dh1T, *dh1n, *dc0, *dc1T, *part0, *part1a, *part1b, *ptab, *embT, *wt, *wt4;
    __half *a0h,*a0l,*a1h,*a1l,*w0h,*w0l,*w1h,*w1l;
    cudaGetSymbolAddress((void**)&seq1T, g_seq1T);
    cudaGetSymbolAddress((void**)&y1fT,  g_y1fT);
    cudaGetSymbolAddress((void**)&y1bT,  g_y1bT);
    cudaGetSymbolAddress((void**)&preF,  g_preF);
    cudaGetSymbolAddress((void**)&preB,  g_preB);
    cudaGetSymbolAddress((void**)&c0fT,  g_c0fT);
    cudaGetSymbolAddress((void**)&c0bT,  g_c0bT);
    cudaGetSymbolAddress((void**)&c1fT,  g_c1fT);
    cudaGetSymbolAddress((void**)&c1bT,  g_c1bT);
    cudaGetSymbolAddress((void**)&zeros, g_zeros);
    cudaGetSymbolAddress((void**)&zbuf,  g_z);
    cudaGetSymbolAddress((void**)&dh0T,  g_dh0T);
    cudaGetSymbolAddress((void**)&dh1T,  g_dh1T);
    cudaGetSymbolAddress((void**)&dh1n,  g_dh1n);
    cudaGetSymbolAddress((void**)&dc0,   g_dc0);
    cudaGetSymbolAddress((void**)&dc1T,  g_dc1T);
    cudaGetSymbolAddress((void**)&part0, g_part0);
    cudaGetSymbolAddress((void**)&part1a,g_part1a);
    cudaGetSymbolAddress((void**)&part1b,g_part1b);
    cudaGetSymbolAddress((void**)&ptab,  g_ptab);
    cudaGetSymbolAddress((void**)&embT,  g_embT);
    cudaGetSymbolAddress((void**)&wt,    g_wt);
    cudaGetSymbolAddress((void**)&wt4,   g_wt4);
    cudaGetSymbolAddress((void**)&a0h, g_a0h); cudaGetSymbolAddress((void**)&a0l, g_a0l);
    cudaGetSymbolAddress((void**)&a1h, g_a1h); cudaGetSymbolAddress((void**)&a1l, g_a1l);
    cudaGetSymbolAddress((void**)&w0h, g_w0h); cudaGetSymbolAddress((void**)&w0l, g_w0l);
    cudaGetSymbolAddress((void**)&w1h, g_w1h); cudaGetSymbolAddress((void**)&w1l, g_w1l);

    const size_t M1 = 1024*1024;
    float* wtPt  = wt;
    float* wtD0  = wt + 1*M1;
    float* wtD1  = wt + 2*M1;
    float* w4e0f = wt4;
    float* w4e0b = wt4 + 1*M1;
    float* w4e1f = wt4 + 2*M1;
    float* w4e1b = wt4 + 3*M1;
    float* w4ih1 = wt4 + 4*M1;
    float* w4hh0 = wt4 + 5*M1;
    float* w4hh1 = wt4 + 6*M1;

    const float* dWih0 = dec_wih;
    const float* dWih1 = dec_wih + (size_t)GG*HH;
    const float* dWhh0 = dec_whh;
    const float* dWhh1 = dec_whh + (size_t)GG*HH;
    const float* db0   = dec_b;
    const float* db1   = dec_b + GG;

    const int MMH = 2*HM_STAGE;   // 61440 B
    cudaFuncSetAttribute(mma_hm, cudaFuncAttributeMaxDynamicSharedMemorySize, MMH);

    // ---- transforms + fp16 splits ----
    embsplit2<<<2048, 256>>>(x, emb, a0h, a0l);
    wsplit2<<<2048, 256>>>(enc_wih_l0, w0h, w0l, 2*GG*HH);
    wsplit2<<<4096, 256>>>(enc_wih_l1, w1h, w1l, 2*GG*2*HH);
    wt_kernel<<<512, 256>>>(emb, embT, VV, HH);
    wt_kernel<<<1024, 256>>>(dWih0, wtPt, GG, HH);
    wt_kernel<<<1024, 256>>>(dWhh0, wtD0, GG, HH);
    wt_kernel<<<1024, 256>>>(dWhh1, wtD1, GG, HH);
    wt4_kernel<<<1024, 256>>>(enc_whh_l0,                 w4e0f);
    wt4_kernel<<<1024, 256>>>(enc_whh_l0 + (size_t)GG*HH, w4e0b);
    wt4_kernel<<<1024, 256>>>(enc_whh_l1,                 w4e1f);
    wt4_kernel<<<1024, 256>>>(enc_whh_l1 + (size_t)GG*HH, w4e1b);
    wt4_kernel<<<1024, 256>>>(dWih1, w4ih1);
    wt4_kernel<<<1024, 256>>>(dWhh0, w4hh0);
    wt4_kernel<<<1024, 256>>>(dWhh1, w4hh1);

    // ---- Ptab ----
    sgemm_ca<<<dim3(GG/128, VV/128), 256>>>(embT, wtPt, db0, ptab, VV, GG, HH);

    // ---- encoder layer 0 pre-GEMMs on HMMA ----
    dim3 hmGrd(GG/64, LDH/128);
    mma_hm<<<hmGrd, 256, MMH>>>(a0h, a0l, w0h, w0l, enc_b_l0,      preF, GG, HH);
    mma_hm<<<hmGrd, 256, MMH>>>(a0h, a0l, w0h + (size_t)GG*HH, w0l + (size_t)GG*HH,
                                enc_b_l0 + GG, preB, GG, HH);

    dim3 stepGrd(HH/32, BB/64, 2);
    float* seq1Tb = seq1T + (size_t)HH*LDH;
    for (int s = 0; s < TT; s++) {
        int tf = s, tb = TT-1-s;
        DirT df = { preF + (size_t)tf*BB*GG,
                    s ? seq1T + (size_t)(tf-1)*BB : zeros, s ? LDH : BB,
                    s ? c0fT : zeros, c0fT,
                    seq1T + (size_t)tf*BB, w4e0f,
                    a1h + (size_t)tf*BB*1024, a1l + (size_t)tf*BB*1024 };
        DirT db = { preB + (size_t)tb*BB*GG,
                    s ? seq1Tb + (size_t)(tb+1)*BB : zeros, s ? LDH : BB,
                    s ? c0bT : zeros, c0bT,
                    seq1Tb + (size_t)tb*BB, w4e0b,
                    a1h + (size_t)tb*BB*1024 + 512, a1l + (size_t)tb*BB*1024 + 512 };
        lstm_stepT<<<stepGrd, 512>>>(df, db);
    }

    // ---- encoder layer 1 pre-GEMMs on HMMA (K=1024) ----
    mma_hm<<<hmGrd, 256, MMH>>>(a1h, a1l, w1h, w1l, enc_b_l1,      preF, GG, 2*HH);
    mma_hm<<<hmGrd, 256, MMH>>>(a1h, a1l, w1h + (size_t)GG*2*HH, w1l + (size_t)GG*2*HH,
                                enc_b_l1 + GG, preB, GG, 2*HH);
    for (int s = 0; s < TT; s++) {
        int tf = s, tb = TT-1-s;
        DirT df = { preF + (size_t)tf*BB*GG,
                    s ? y1fT + (size_t)(tf-1)*BB : zeros, s ? LDH : BB,
                    s ? c1fT : zeros, c1fT,
                    y1fT + (size_t)tf*BB, w4e1f, nullptr, nullptr };
        DirT db = { preB + (size_t)tb*BB*GG,
                    s ? y1bT + (size_t)(tb+1)*BB : zeros, s ? LDH : BB,
                    s ? c1bT : zeros, c1bT,
                    y1bT + (size_t)tb*BB, w4e1b, nullptr, nullptr };
        lstm_stepT<<<stepGrd, 512>>>(df, db);
    }

    // ---- heads ----
    head_kernel<<<BB, 256>>>(y1fT + (size_t)(TT-1)*BB, y1bT,
                             fc_mu_w, fc_mu_b, fc_lv_w, fc_lv_b,
                             out_mu, out_lv, zbuf);

    // ---- decoder init ----
    dec_init_kernel<<<BB, 512>>>(zbuf, dec_in_w, dec_in_b, dh0T, dh1T, dh1n, dc0, dc1T);
    dim3 partGrd(GG/128, BB/128);
    sgemm_ca<<<partGrd, 256>>>(dh0T, wtD0, zeros, part0,  BB, GG, HH);
    sgemm_ca<<<partGrd, 256>>>(dh1T, wtD1, db1,   part1a, BB, GG, HH);
    cudaMemsetAsync(part1b, 0, (size_t)BB*GG*sizeof(float));
    cell0_init_kernel<<<BB, 128>>>(ptab, part0, dc0, dh0T);

    // ---- autoregressive decode ----
    dim3 yGrd(HH/32, BB/64, 2);
    dim3 zGrd(HH/32, BB/64, 3);
    for (int t = 0; t < TT; t++) {
        dec_Y<<<yGrd, 512>>>(dh0T, w4ih1, part1a, part1b, dc1T, dh1T, dh1n,
                             w4hh0, zeros, part0);
        dec_Z<<<zGrd, 512>>>(dh1T, dh1n, dec_out_w, dec_out_b, w4hh1, db1, zeros,
                             part1a, part1b, ptab, part0, dc0, dh0T, out_recon, t);
    }
}